// round 1
// baseline (speedup 1.0000x reference)
#include <cuda_runtime.h>
#include <math.h>

#define BB 2
#define NN 2048
#define DDIM 128
#define KNBR 128
#define NLAYER 4
#define PP (BB*NN)          // 4096 points total
#define HCAT 259            // 3 + 128 + 128

// ---------------- scratch (device globals; no allocation allowed) ----------------
__device__ int   g_idx[PP*KNBR];        // global neighbor row index (b*N+m)
__device__ float g_rel[PP*KNBR*3];      // xyz[n] - xyz[m]
__device__ float g_v[PP*DDIM];
__device__ float g_qs[PP];
__device__ float g_ks[PP];
__device__ float g_aggv[PP*DDIM];
__device__ float g_aggh[PP*DDIM];
__device__ float g_t1[PP*DDIM];
__device__ float g_fA[PP*DDIM];
__device__ float g_fB[PP*DDIM];
__device__ float g_wqcs[DDIM];
__device__ float g_wkcs[DDIM];
__device__ float g_w2cs[DDIM];
__device__ float g_scal[4];             // [0]=sum bq, [1]=sum bk, [2]=sum bp2
__device__ float g_temb[BB*DDIM];
__device__ float g_h[PP*HCAT];
__device__ float g_h1[PP*DDIM];
__device__ float g_h2[PP*DDIM];

// ---------------- KNN: one CTA (256 thr) per point; exact top-128 with
// JAX tie-breaking (equal dist -> smaller index) via binary search on float bits.
__global__ void knn_kernel(const float* __restrict__ xyz) {
    int p = blockIdx.x;
    int b = p >> 11;          // /2048
    int n = p & 2047;
    const float* X = xyz + (size_t)b * NN * 3;

    __shared__ float dsh[NN];
    __shared__ int   red[8];
    __shared__ int   slot;

    int tid  = threadIdx.x;
    int lane = tid & 31, wid = tid >> 5;

    float x0 = X[n*3+0], y0 = X[n*3+1], z0 = X[n*3+2];
    float sq0 = x0*x0 + y0*y0 + z0*z0;

    unsigned ul[8];
    #pragma unroll
    for (int i = 0; i < 8; i++) {
        int m = tid + (i << 8);
        float xm = X[m*3+0], ym = X[m*3+1], zm = X[m*3+2];
        float sqm = xm*xm + ym*ym + zm*zm;
        float dot = x0*xm + y0*ym + z0*zm;
        float d = sq0 + sqm - 2.0f*dot;
        dsh[m] = d;
        unsigned u = __float_as_uint(d);
        ul[i] = (u & 0x80000000u) ? ~u : (u | 0x80000000u);   // order-preserving map
    }
    __syncthreads();

    // binary search for 128th smallest transformed key
    unsigned lo = 0u, hi = 0xFFFFFFFFu;
    while (lo < hi) {
        unsigned mid = lo + ((hi - lo) >> 1);
        int c = 0;
        #pragma unroll
        for (int i = 0; i < 8; i++) c += (ul[i] <= mid);
        #pragma unroll
        for (int o = 16; o; o >>= 1) c += __shfl_xor_sync(0xffffffffu, c, o);
        if (!lane) red[wid] = c;
        __syncthreads();
        int tot = red[0]+red[1]+red[2]+red[3]+red[4]+red[5]+red[6]+red[7];
        if (tot >= KNBR) hi = mid; else lo = mid + 1;
        __syncthreads();
    }
    unsigned ustar = lo;

    // count strictly-less
    int c2 = 0;
    #pragma unroll
    for (int i = 0; i < 8; i++) c2 += (ul[i] < ustar);
    #pragma unroll
    for (int o = 16; o; o >>= 1) c2 += __shfl_xor_sync(0xffffffffu, c2, o);
    if (!lane) red[wid] = c2;
    __syncthreads();
    int c_lt = red[0]+red[1]+red[2]+red[3]+red[4]+red[5]+red[6]+red[7];
    int r = KNBR - c_lt;     // take r of the equals, by smallest index

    if (tid == 0) slot = 0;
    __syncthreads();

    #pragma unroll
    for (int i = 0; i < 8; i++) {
        int m = tid + (i << 8);
        bool sel = false;
        if (ul[i] < ustar) sel = true;
        else if (ul[i] == ustar && r > 0) {
            unsigned mybits = __float_as_uint(dsh[m]);
            int rk = 0;
            for (int mm = 0; mm < m; ++mm)
                rk += (__float_as_uint(dsh[mm]) == mybits);
            if (rk < r) sel = true;
        }
        if (sel) {
            int s = atomicAdd(&slot, 1);
            size_t base = (size_t)p * KNBR + s;
            g_idx[base] = b * NN + m;
            g_rel[base*3+0] = x0 - X[m*3+0];
            g_rel[base*3+1] = y0 - X[m*3+1];
            g_rel[base*3+2] = z0 - X[m*3+2];
        }
    }
}

// ---------------- per-layer prep: column sums of Wq/Wk (sum over out-dim) and Wp2 row-sums
__global__ void prep_kernel(const float* __restrict__ Wq, const float* __restrict__ bq,
                            const float* __restrict__ Wk, const float* __restrict__ bk,
                            const float* __restrict__ Wp2, const float* __restrict__ bp2) {
    int i = threadIdx.x;   // 128
    float a = 0.f, b2 = 0.f, c = 0.f;
    for (int d = 0; d < DDIM; d++) {
        a  += Wq[i*DDIM + d];
        b2 += Wk[i*DDIM + d];
        c  += Wp2[i*DDIM + d];
    }
    g_wqcs[i] = a; g_wkcs[i] = b2; g_w2cs[i] = c;
    if (i == 0) {
        float sa = 0.f, sb = 0.f, sc = 0.f;
        for (int d = 0; d < DDIM; d++) { sa += bq[d]; sb += bk[d]; sc += bp2[d]; }
        g_scal[0] = sa; g_scal[1] = sb; g_scal[2] = sc;
    }
}

// ---------------- per-point q/k scalars: one warp per point
__global__ void qsks_kernel(const float* __restrict__ feat) {
    int p = blockIdx.x * 8 + (threadIdx.x >> 5);
    int lane = threadIdx.x & 31;
    float4 f  = ((const float4*)(feat + (size_t)p * DDIM))[lane];
    float4 wq = ((const float4*)g_wqcs)[lane];
    float4 wk = ((const float4*)g_wkcs)[lane];
    float q = f.x*wq.x + f.y*wq.y + f.z*wq.z + f.w*wq.w;
    float k = f.x*wk.x + f.y*wk.y + f.z*wk.z + f.w*wk.w;
    #pragma unroll
    for (int o = 16; o; o >>= 1) {
        q += __shfl_xor_sync(0xffffffffu, q, o);
        k += __shfl_xor_sync(0xffffffffu, k, o);
    }
    if (!lane) { g_qs[p] = q + g_scal[0]; g_ks[p] = k + g_scal[1]; }
}

// ---------------- attention kernel: one CTA (128 thr) per point
// phase1: thread k computes h1_k[0..127] + logit; phase2: softmax over K;
// phase3: thread d aggregates attn-weighted v-gather and h1.
#define H1STRIDE 132
#define ATTN_SMEM_FLOATS (KNBR*H1STRIDE + 384 + 128 + 128 + 128 + 128 + 8)
#define ATTN_SMEM_BYTES  (ATTN_SMEM_FLOATS * 4)

__global__ void attn_kernel(const float* __restrict__ Wp1, const float* __restrict__ bp1) {
    extern __shared__ float sm[];
    float* h1s  = sm;                          // 128*132
    float* wp1s = sm + KNBR*H1STRIDE;          // 384
    float* bp1s = wp1s + 384;                  // 128
    float* w2s  = bp1s + 128;                  // 128
    float* attw = w2s + 128;                   // 128
    int*   ids  = (int*)(attw + 128);          // 128
    float* red  = (float*)(ids + 128);         // 8

    int p = blockIdx.x;
    int tid = threadIdx.x;                     // 128
    int lane = tid & 31, wid = tid >> 5;

    wp1s[tid]       = Wp1[tid];
    wp1s[tid + 128] = Wp1[tid + 128];
    wp1s[tid + 256] = Wp1[tid + 256];
    bp1s[tid] = bp1[tid];
    w2s[tid]  = g_w2cs[tid];
    __syncthreads();

    // ---- phase 1
    int k = tid;
    size_t base = (size_t)p * KNBR + k;
    int gm = g_idx[base];
    ids[k] = gm;
    float rx = g_rel[base*3+0], ry = g_rel[base*3+1], rz = g_rel[base*3+2];

    const float4* wx4 = (const float4*)wp1s;
    const float4* wy4 = (const float4*)(wp1s + 128);
    const float4* wz4 = (const float4*)(wp1s + 256);
    const float4* bp4 = (const float4*)bp1s;
    const float4* w24 = (const float4*)w2s;
    float4* h1row = (float4*)&h1s[k * H1STRIDE];

    float dot = 0.f;
    #pragma unroll 8
    for (int j = 0; j < 32; j++) {
        float4 h = bp4[j];
        float4 wx = wx4[j], wy = wy4[j], wz = wz4[j], w2 = w24[j];
        h.x = fmaf(rx, wx.x, h.x); h.x = fmaf(ry, wy.x, h.x); h.x = fmaf(rz, wz.x, h.x); h.x = fmaxf(h.x, 0.f);
        h.y = fmaf(rx, wx.y, h.y); h.y = fmaf(ry, wy.y, h.y); h.y = fmaf(rz, wz.y, h.y); h.y = fmaxf(h.y, 0.f);
        h.z = fmaf(rx, wx.z, h.z); h.z = fmaf(ry, wy.z, h.z); h.z = fmaf(rz, wz.z, h.z); h.z = fmaxf(h.z, 0.f);
        h.w = fmaf(rx, wx.w, h.w); h.w = fmaf(ry, wy.w, h.w); h.w = fmaf(rz, wz.w, h.w); h.w = fmaxf(h.w, 0.f);
        h1row[j] = h;
        dot = fmaf(h.x, w2.x, dot); dot = fmaf(h.y, w2.y, dot);
        dot = fmaf(h.z, w2.z, dot); dot = fmaf(h.w, w2.w, dot);
    }
    float logit = g_qs[p] - g_ks[gm] + dot + g_scal[2];

    // ---- phase 2: softmax over K (128 values, 4 warps)
    float mx = logit;
    #pragma unroll
    for (int o = 16; o; o >>= 1) mx = fmaxf(mx, __shfl_xor_sync(0xffffffffu, mx, o));
    if (!lane) red[wid] = mx;
    __syncthreads();
    mx = fmaxf(fmaxf(red[0], red[1]), fmaxf(red[2], red[3]));
    float e = expf(logit - mx);
    float ss = e;
    #pragma unroll
    for (int o = 16; o; o >>= 1) ss += __shfl_xor_sync(0xffffffffu, ss, o);
    if (!lane) red[4 + wid] = ss;
    __syncthreads();
    ss = red[4] + red[5] + red[6] + red[7];
    attw[tid] = e / ss;
    __syncthreads();

    // ---- phase 3: thread d aggregates over k
    int d = tid;
    float accv = 0.f, acch = 0.f;
    #pragma unroll 8
    for (int k2 = 0; k2 < KNBR; k2++) {
        float a = attw[k2];
        int gm2 = ids[k2];
        accv = fmaf(a, g_v[(size_t)gm2 * DDIM + d], accv);
        acch = fmaf(a, h1s[k2 * H1STRIDE + d], acch);
    }
    g_aggv[(size_t)p * DDIM + d] = accv;
    g_aggh[(size_t)p * DDIM + d] = acch;
}

// ---------------- generic M x K @ K x 128 GEMM, BM=32, BN=128, 256 threads,
// 4x4 register micro-tiles. MODE: 0=bias, 1=bias+Add, 2=Res+gamma*(acc+bias),
// 3=LayerNorm(acc+bias)*g+beta then ReLU (row = 128 cols lives in one warp).
template<int MODE>
__global__ void gemm128(const float* __restrict__ A, int K, int KP,
                        const float* __restrict__ W,
                        const float* __restrict__ bias,
                        float* __restrict__ C,
                        const float* __restrict__ Add,
                        const float* __restrict__ Res,
                        const float* __restrict__ gammaPtr,
                        const float* __restrict__ g,
                        const float* __restrict__ beta) {
    extern __shared__ float sm[];
    float* As = sm;                 // 32*KP
    float* Ws = sm + 32 * KP;       // 32*132

    int row0 = blockIdx.x * 32;
    int tid = threadIdx.x;          // 256
    int tx = tid & 31, ty = tid >> 5;

    for (int i = tid; i < 32 * KP; i += 256) {
        int rr = i / KP, kk = i % KP;
        As[i] = (kk < K) ? A[(size_t)(row0 + rr) * K + kk] : 0.f;
    }

    float acc[4][4];
    #pragma unroll
    for (int a = 0; a < 4; a++)
        #pragma unroll
        for (int b = 0; b < 4; b++) acc[a][b] = 0.f;

    int ntiles = KP / 32;
    for (int kb = 0; kb < ntiles; kb++) {
        __syncthreads();
        for (int i = tid; i < 32 * 128; i += 256) {
            int kk = i >> 7, c = i & 127;
            int kg = kb * 32 + kk;
            Ws[kk * 132 + c] = (kg < K) ? W[(size_t)kg * 128 + c] : 0.f;
        }
        __syncthreads();
        #pragma unroll
        for (int kk = 0; kk < 32; kk += 4) {
            float4 w0 = *(float4*)&Ws[(kk+0)*132 + tx*4];
            float4 w1 = *(float4*)&Ws[(kk+1)*132 + tx*4];
            float4 w2 = *(float4*)&Ws[(kk+2)*132 + tx*4];
            float4 w3 = *(float4*)&Ws[(kk+3)*132 + tx*4];
            #pragma unroll
            for (int rr = 0; rr < 4; rr++) {
                float4 a = *(float4*)&As[(ty*4+rr)*KP + kb*32 + kk];
                acc[rr][0] = fmaf(a.x,w0.x,fmaf(a.y,w1.x,fmaf(a.z,w2.x,fmaf(a.w,w3.x,acc[rr][0]))));
                acc[rr][1] = fmaf(a.x,w0.y,fmaf(a.y,w1.y,fmaf(a.z,w2.y,fmaf(a.w,w3.y,acc[rr][1]))));
                acc[rr][2] = fmaf(a.x,w0.z,fmaf(a.y,w1.z,fmaf(a.z,w2.z,fmaf(a.w,w3.z,acc[rr][2]))));
                acc[rr][3] = fmaf(a.x,w0.w,fmaf(a.y,w1.w,fmaf(a.z,w2.w,fmaf(a.w,w3.w,acc[rr][3]))));
            }
        }
    }

    int col0 = tx * 4;
    float4 bb = *(const float4*)&bias[col0];
    float gmv = 0.f;
    if (MODE == 2) gmv = __ldg(gammaPtr);
    float4 g4, be4;
    if (MODE == 3) { g4 = *(const float4*)&g[col0]; be4 = *(const float4*)&beta[col0]; }

    #pragma unroll
    for (int rr = 0; rr < 4; rr++) {
        int row = row0 + ty * 4 + rr;
        float v0 = acc[rr][0] + bb.x;
        float v1 = acc[rr][1] + bb.y;
        float v2 = acc[rr][2] + bb.z;
        float v3 = acc[rr][3] + bb.w;
        if (MODE == 1) {
            float4 ad = *(const float4*)&Add[(size_t)row * 128 + col0];
            v0 += ad.x; v1 += ad.y; v2 += ad.z; v3 += ad.w;
        }
        if (MODE == 2) {
            float4 rs = *(const float4*)&Res[(size_t)row * 128 + col0];
            v0 = rs.x + gmv * v0; v1 = rs.y + gmv * v1;
            v2 = rs.z + gmv * v2; v3 = rs.w + gmv * v3;
        }
        if (MODE == 3) {
            float s = v0 + v1 + v2 + v3;
            #pragma unroll
            for (int o = 16; o; o >>= 1) s += __shfl_xor_sync(0xffffffffu, s, o);
            float mean = s * 0.0078125f;
            float d0 = v0 - mean, d1 = v1 - mean, d2 = v2 - mean, d3 = v3 - mean;
            float q = d0*d0 + d1*d1 + d2*d2 + d3*d3;
            #pragma unroll
            for (int o = 16; o; o >>= 1) q += __shfl_xor_sync(0xffffffffu, q, o);
            float rstd = rsqrtf(q * 0.0078125f + 1e-5f);
            v0 = fmaxf(fmaf(d0 * rstd, g4.x, be4.x), 0.f);
            v1 = fmaxf(fmaf(d1 * rstd, g4.y, be4.y), 0.f);
            v2 = fmaxf(fmaf(d2 * rstd, g4.z, be4.z), 0.f);
            v3 = fmaxf(fmaf(d3 * rstd, g4.w, be4.w), 0.f);
        }
        *(float4*)&C[(size_t)row * 128 + col0] = make_float4(v0, v1, v2, v3);
    }
}

// ---------------- DDPM timestep embedding + 2-layer MLP (B=2)
__global__ void temb_kernel(const int* __restrict__ t,
                            const float* __restrict__ tW1, const float* __restrict__ tb1,
                            const float* __restrict__ tW2, const float* __restrict__ tb2) {
    __shared__ float emb[128], h1[128];
    int b = blockIdx.x, d = threadIdx.x;
    float tv = (float)t[b];
    if (d < 64) {
        float f = expf(-logf(10000.f) * (float)d / 63.f);
        float arg = tv * f;
        emb[d] = sinf(arg);
        emb[d + 64] = cosf(arg);
    }
    __syncthreads();
    float a = tb1[d];
    for (int i = 0; i < 128; i++) a = fmaf(emb[i], tW1[i*128 + d], a);
    h1[d] = fmaxf(a, 0.f);
    __syncthreads();
    float c = tb2[d];
    for (int i = 0; i < 128; i++) c = fmaf(h1[i], tW2[i*128 + d], c);
    g_temb[b*128 + d] = c;
}

// ---------------- concat [x_t | fused | temb] -> g_h [P,259]
__global__ void concat_kernel(const float* __restrict__ x_t, const float* __restrict__ fused) {
    int p = blockIdx.x;
    int b = p >> 11;
    for (int c = threadIdx.x; c < HCAT; c += blockDim.x) {
        float v;
        if (c < 3)        v = x_t[(size_t)p*3 + c];
        else if (c < 131) v = fused[(size_t)p*DDIM + (c - 3)];
        else              v = g_temb[b*DDIM + (c - 131)];
        g_h[(size_t)p*HCAT + c] = v;
    }
}

// ---------------- final projection to 3 dims: one warp per point
__global__ void out_kernel(const float* __restrict__ W3, const float* __restrict__ b3,
                           float* __restrict__ out) {
    int p = blockIdx.x * 8 + (threadIdx.x >> 5);
    int lane = threadIdx.x & 31;
    float4 f = ((const float4*)(g_h2 + (size_t)p * DDIM))[lane];
    int i0 = lane * 4;
    float a0 = f.x*W3[i0*3+0] + f.y*W3[(i0+1)*3+0] + f.z*W3[(i0+2)*3+0] + f.w*W3[(i0+3)*3+0];
    float a1 = f.x*W3[i0*3+1] + f.y*W3[(i0+1)*3+1] + f.z*W3[(i0+2)*3+1] + f.w*W3[(i0+3)*3+1];
    float a2 = f.x*W3[i0*3+2] + f.y*W3[(i0+1)*3+2] + f.z*W3[(i0+2)*3+2] + f.w*W3[(i0+3)*3+2];
    #pragma unroll
    for (int o = 16; o; o >>= 1) {
        a0 += __shfl_xor_sync(0xffffffffu, a0, o);
        a1 += __shfl_xor_sync(0xffffffffu, a1, o);
        a2 += __shfl_xor_sync(0xffffffffu, a2, o);
    }
    if (!lane) {
        out[p*3+0] = a0 + b3[0];
        out[p*3+1] = a1 + b3[1];
        out[p*3+2] = a2 + b3[2];
    }
}

#define GEMM_SMEM(KP) ((32*(KP) + 32*132) * 4)

extern "C" void kernel_launch(void* const* d_in, const int* in_sizes, int n_in,
                              void* d_out, int out_size) {
    const float* xyz   = (const float*)d_in[0];
    const float* feat  = (const float*)d_in[1];
    const float* x_t   = (const float*)d_in[2];
    const int*   t     = (const int*)  d_in[3];
    const float* Wq    = (const float*)d_in[4];
    const float* bq    = (const float*)d_in[5];
    const float* Wk    = (const float*)d_in[6];
    const float* bk    = (const float*)d_in[7];
    const float* Wv    = (const float*)d_in[8];
    const float* bv    = (const float*)d_in[9];
    const float* Wp1   = (const float*)d_in[10];
    const float* bp1   = (const float*)d_in[11];
    const float* Wp2   = (const float*)d_in[12];
    const float* bp2   = (const float*)d_in[13];
    const float* gamma = (const float*)d_in[14];
    const float* Wproj = (const float*)d_in[15];
    const float* bproj = (const float*)d_in[16];
    const float* tW1   = (const float*)d_in[17];
    const float* tb1   = (const float*)d_in[18];
    const float* tW2   = (const float*)d_in[19];
    const float* tb2   = (const float*)d_in[20];
    const float* nW1   = (const float*)d_in[21];
    const float* nb1   = (const float*)d_in[22];
    const float* ng1   = (const float*)d_in[23];
    const float* nbe1  = (const float*)d_in[24];
    const float* nW2   = (const float*)d_in[25];
    const float* nb2   = (const float*)d_in[26];
    const float* ng2   = (const float*)d_in[27];
    const float* nbe2  = (const float*)d_in[28];
    const float* nW3   = (const float*)d_in[29];
    const float* nb3   = (const float*)d_in[30];

    cudaFuncSetAttribute(attn_kernel, cudaFuncAttributeMaxDynamicSharedMemorySize, ATTN_SMEM_BYTES);
    cudaFuncSetAttribute(gemm128<3>,  cudaFuncAttributeMaxDynamicSharedMemorySize, GEMM_SMEM(288));

    float *pv, *paggv, *paggh, *pt1, *pfA, *pfB, *ph, *ph1, *ph2;
    cudaGetSymbolAddress((void**)&pv,    g_v);
    cudaGetSymbolAddress((void**)&paggv, g_aggv);
    cudaGetSymbolAddress((void**)&paggh, g_aggh);
    cudaGetSymbolAddress((void**)&pt1,   g_t1);
    cudaGetSymbolAddress((void**)&pfA,   g_fA);
    cudaGetSymbolAddress((void**)&pfB,   g_fB);
    cudaGetSymbolAddress((void**)&ph,    g_h);
    cudaGetSymbolAddress((void**)&ph1,   g_h1);
    cudaGetSymbolAddress((void**)&ph2,   g_h2);

    knn_kernel<<<PP, 256>>>(xyz);

    const float* cur = feat;
    float* bufs[2] = { pfA, pfB };
    for (int l = 0; l < NLAYER; l++) {
        prep_kernel<<<1, 128>>>(Wq + l*DDIM*DDIM, bq + l*DDIM,
                                Wk + l*DDIM*DDIM, bk + l*DDIM,
                                Wp2 + l*DDIM*DDIM, bp2 + l*DDIM);
        qsks_kernel<<<PP/8, 256>>>(cur);
        gemm128<0><<<PP/32, 256, GEMM_SMEM(128)>>>(cur, 128, 128,
            Wv + l*DDIM*DDIM, bv + l*DDIM, pv,
            nullptr, nullptr, nullptr, nullptr, nullptr);
        attn_kernel<<<PP, 128, ATTN_SMEM_BYTES>>>(Wp1 + l*3*DDIM, bp1 + l*DDIM);
        gemm128<1><<<PP/32, 256, GEMM_SMEM(128)>>>(paggh, 128, 128,
            Wp2 + l*DDIM*DDIM, bp2 + l*DDIM, pt1,
            paggv, nullptr, nullptr, nullptr, nullptr);
        float* nxt = bufs[l & 1];
        gemm128<2><<<PP/32, 256, GEMM_SMEM(128)>>>(pt1, 128, 128,
            Wproj + l*DDIM*DDIM, bproj + l*DDIM, nxt,
            nullptr, cur, gamma + l, nullptr, nullptr);
        cur = nxt;
    }

    temb_kernel<<<BB, 128>>>(t, tW1, tb1, tW2, tb2);
    concat_kernel<<<PP, 128>>>(x_t, cur);
    gemm128<3><<<PP/32, 256, GEMM_SMEM(288)>>>(ph, HCAT, 288,
        nW1, nb1, ph1, nullptr, nullptr, nullptr, ng1, nbe1);
    gemm128<3><<<PP/32, 256, GEMM_SMEM(128)>>>(ph1, 128, 128,
        nW2, nb2, ph2, nullptr, nullptr, nullptr, ng2, nbe2);
    out_kernel<<<PP/8, 256>>>(nW3, nb3, (float*)d_out);
}

// round 2
// speedup vs baseline: 1.2394x; 1.2394x over previous
#include <cuda_runtime.h>
#include <math.h>

#define BB 2
#define NN 2048
#define DDIM 128
#define KNBR 128
#define NLAYER 4
#define PP (BB*NN)          // 4096 points
#define HCAT 259            // 3 + 128 + 128

// ---------------- scratch (device globals) ----------------
__device__ int    g_idx[PP*KNBR];
__device__ float4 g_rel4[PP*KNBR];      // (rx,ry,rz, scratch)
__device__ float  g_v[PP*DDIM];
__device__ float  g_qs[PP];
__device__ float  g_ks[PP];
__device__ float  g_aggv[PP*DDIM];
__device__ float  g_aggh[PP*DDIM];
__device__ float  g_t1[PP*DDIM];
__device__ float  g_fA[PP*DDIM];
__device__ float  g_fB[PP*DDIM];
__device__ float  g_wqcs[NLAYER*DDIM];
__device__ float  g_wkcs[NLAYER*DDIM];
__device__ float  g_w2cs[NLAYER*DDIM];
__device__ float  g_scal[NLAYER*4];     // per layer: sum bq, sum bk, sum bp2
__device__ float  g_temb[BB*DDIM];
__device__ float  g_h[PP*HCAT];
__device__ float  g_h1[PP*DDIM];        // raw (pre-LN) head layer 1
__device__ float  g_h2[PP*DDIM];        // raw (pre-LN) head layer 2

// ================= KNN: one CTA (256 thr) per point =================
__global__ void knn_kernel(const float* __restrict__ xyz) {
    __shared__ float xs[NN*3];     // 24KB
    __shared__ float dsh[NN];      // 8KB
    __shared__ int   red[8];
    __shared__ int   slot;

    int p = blockIdx.x;
    int b = p >> 11;
    int n = p & 2047;
    int tid  = threadIdx.x;
    int lane = tid & 31, wid = tid >> 5;

    const float4* X4 = (const float4*)(xyz + (size_t)b * NN * 3);
    float4* xs4 = (float4*)xs;
    #pragma unroll
    for (int i = tid; i < (NN*3)/4; i += 256) xs4[i] = X4[i];
    __syncthreads();

    float x0 = xs[n*3+0], y0 = xs[n*3+1], z0 = xs[n*3+2];
    float sq0 = x0*x0 + y0*y0 + z0*z0;

    unsigned ul[8];
    #pragma unroll
    for (int i = 0; i < 8; i++) {
        int m = tid + (i << 8);
        float xm = xs[m*3+0], ym = xs[m*3+1], zm = xs[m*3+2];
        float sqm = xm*xm + ym*ym + zm*zm;
        float dot = x0*xm + y0*ym + z0*zm;
        float d = sq0 + sqm - 2.0f*dot;
        dsh[m] = d;
        unsigned u = __float_as_uint(d);
        ul[i] = (u & 0x80000000u) ? ~u : (u | 0x80000000u);
    }
    __syncthreads();

    // binary search for 128th smallest transformed key
    unsigned lo = 0u, hi = 0xFFFFFFFFu;
    while (lo < hi) {
        unsigned mid = lo + ((hi - lo) >> 1);
        int c = 0;
        #pragma unroll
        for (int i = 0; i < 8; i++) c += (ul[i] <= mid);
        #pragma unroll
        for (int o = 16; o; o >>= 1) c += __shfl_xor_sync(0xffffffffu, c, o);
        if (!lane) red[wid] = c;
        __syncthreads();
        int tot = red[0]+red[1]+red[2]+red[3]+red[4]+red[5]+red[6]+red[7];
        if (tot >= KNBR) hi = mid; else lo = mid + 1;
        __syncthreads();
    }
    unsigned ustar = lo;

    int c2 = 0;
    #pragma unroll
    for (int i = 0; i < 8; i++) c2 += (ul[i] < ustar);
    #pragma unroll
    for (int o = 16; o; o >>= 1) c2 += __shfl_xor_sync(0xffffffffu, c2, o);
    if (!lane) red[wid] = c2;
    __syncthreads();
    int c_lt = red[0]+red[1]+red[2]+red[3]+red[4]+red[5]+red[6]+red[7];
    int r = KNBR - c_lt;

    if (tid == 0) slot = 0;
    __syncthreads();

    #pragma unroll
    for (int i = 0; i < 8; i++) {
        int m = tid + (i << 8);
        bool sel = false;
        if (ul[i] < ustar) sel = true;
        else if (ul[i] == ustar && r > 0) {
            unsigned mybits = __float_as_uint(dsh[m]);
            int rk = 0;
            for (int mm = 0; mm < m; ++mm)
                rk += (__float_as_uint(dsh[mm]) == mybits);
            if (rk < r) sel = true;
        }
        if (sel) {
            int s = atomicAdd(&slot, 1);
            size_t o = (size_t)p * KNBR + s;
            g_idx[o] = b * NN + m;
            g_rel4[o] = make_float4(x0 - xs[m*3+0], y0 - xs[m*3+1], z0 - xs[m*3+2], 0.f);
        }
    }
}

// ================= prep for ALL layers in one launch =================
// grid (NLAYER, 4): y=0 Wq rowsums, 1 Wk, 2 Wp2, 3 bias sums. 128 threads.
__global__ void prep_all(const float* __restrict__ Wq, const float* __restrict__ bq,
                         const float* __restrict__ Wk, const float* __restrict__ bk,
                         const float* __restrict__ Wp2, const float* __restrict__ bp2) {
    int l = blockIdx.x, kind = blockIdx.y, tid = threadIdx.x;
    if (kind < 3) {
        const float* W = (kind == 0 ? Wq : kind == 1 ? Wk : Wp2) + (size_t)l * DDIM * DDIM;
        float* dst = (kind == 0 ? g_wqcs : kind == 1 ? g_wkcs : g_w2cs) + l * DDIM;
        int seg = tid & 3;
        int rbase = tid >> 2;
        for (int rr = 0; rr < DDIM; rr += 32) {
            int rrow = rbase + rr;
            const float4* row = (const float4*)(W + (size_t)rrow * DDIM + seg * 32);
            float s = 0.f;
            #pragma unroll
            for (int j = 0; j < 8; j++) { float4 v = row[j]; s += v.x + v.y + v.z + v.w; }
            s += __shfl_xor_sync(0xffffffffu, s, 1);
            s += __shfl_xor_sync(0xffffffffu, s, 2);
            if (seg == 0) dst[rrow] = s;
        }
    } else {
        int w = tid >> 5, lane = tid & 31;
        if (w < 3) {
            const float* bb = (w == 0 ? bq : w == 1 ? bk : bp2) + l * DDIM;
            float s = bb[lane] + bb[lane+32] + bb[lane+64] + bb[lane+96];
            #pragma unroll
            for (int o = 16; o; o >>= 1) s += __shfl_xor_sync(0xffffffffu, s, o);
            if (!lane) g_scal[l*4 + w] = s;
        }
    }
}

// ================= GEMM: C[M,128] = A[M,K] @ W[K,128] (+epilogues) =================
// 128 threads, BM=32, grid (M/32, 2): blockIdx.y selects 64-col half.
// warp handles 8 rows; lane handles 2 cols. Whole W-half resident in smem.
// MODE: 0 = +bias (optional fused qs/ks), 1 = +bias+Add, 2 = Res + gamma*(acc+bias)
// LNA: apply LayerNorm(g,b)+ReLU to A rows in smem before the GEMM (K must be 128).
template<int MODE, bool LNA>
__global__ void __launch_bounds__(128) gemm_k(
    const float* __restrict__ A, int K, int KPp,
    const float* __restrict__ W,
    const float* __restrict__ bias,
    float* __restrict__ C,
    const float* __restrict__ Add,
    const float* __restrict__ Res,
    const float* __restrict__ gammaPtr,
    const float* __restrict__ lng, const float* __restrict__ lnb,
    const float* __restrict__ wq, const float* __restrict__ wk,
    const float* __restrict__ scal2,
    float* __restrict__ qs, float* __restrict__ ks)
{
    extern __shared__ float sm[];
    float* As = sm;                 // 32 * KPp
    float* Ws = sm + 32 * KPp;      // KPp * 64

    int tid = threadIdx.x, tx = tid & 31, wrp = tid >> 5;
    int row0 = blockIdx.x * 32, ny = blockIdx.y;
    int K4 = K >> 2, KP4 = KPp >> 2;

    // ---- load A tile
    if ((K & 3) == 0) {
        const float4* A4 = (const float4*)A;
        float4* As4 = (float4*)As;
        #pragma unroll
        for (int rrow = 0; rrow < 32; rrow++)
            for (int c = tid; c < KP4; c += 128)
                As4[rrow*KP4 + c] = (c < K4) ? A4[(size_t)(row0+rrow)*K4 + c]
                                             : make_float4(0.f,0.f,0.f,0.f);
    } else {
        #pragma unroll
        for (int rrow = 0; rrow < 32; rrow++)
            for (int c = tid; c < KPp; c += 128)
                As[rrow*KPp + c] = (c < K) ? A[(size_t)(row0+rrow)*K + c] : 0.f;
    }

    // ---- load W half
    {
        const float4* W4 = (const float4*)W;      // K rows of 32 float4
        float4* Ws4 = (float4*)Ws;
        for (int i = tid; i < KPp*16; i += 128) {
            int kk = i >> 4, c = i & 15;
            Ws4[i] = (kk < K) ? W4[(size_t)kk*32 + ny*16 + c] : make_float4(0.f,0.f,0.f,0.f);
        }
    }
    __syncthreads();

    // ---- optional LN+ReLU of A rows (K==128 path only)
    if (LNA) {
        int rrow = tid >> 2, seg = tid & 3;
        float* rowp = As + rrow*KPp + seg*32;
        float s = 0.f;
        #pragma unroll
        for (int j = 0; j < 32; j++) s += rowp[j];
        s += __shfl_xor_sync(0xffffffffu, s, 1);
        s += __shfl_xor_sync(0xffffffffu, s, 2);
        float mean = s * 0.0078125f;
        float q = 0.f;
        #pragma unroll
        for (int j = 0; j < 32; j++) { float d = rowp[j] - mean; q = fmaf(d, d, q); }
        q += __shfl_xor_sync(0xffffffffu, q, 1);
        q += __shfl_xor_sync(0xffffffffu, q, 2);
        float rstd = rsqrtf(q * 0.0078125f + 1e-5f);
        #pragma unroll
        for (int j = 0; j < 32; j++) {
            int c = seg*32 + j;
            rowp[j] = fmaxf(fmaf((rowp[j]-mean)*rstd, __ldg(&lng[c]), __ldg(&lnb[c])), 0.f);
        }
        __syncthreads();
    }

    // ---- fused qs/ks (v-gemm only, half 0)
    if (MODE == 0 && qs != nullptr && ny == 0) {
        int rrow = tid >> 2, seg = tid & 3;
        const float* rowp = As + rrow*KPp + seg*32;
        float dq = 0.f, dk = 0.f;
        #pragma unroll
        for (int j = 0; j < 32; j++) {
            float a = rowp[j];
            dq = fmaf(a, __ldg(&wq[seg*32+j]), dq);
            dk = fmaf(a, __ldg(&wk[seg*32+j]), dk);
        }
        dq += __shfl_xor_sync(0xffffffffu, dq, 1);
        dq += __shfl_xor_sync(0xffffffffu, dq, 2);
        dk += __shfl_xor_sync(0xffffffffu, dk, 1);
        dk += __shfl_xor_sync(0xffffffffu, dk, 2);
        if (seg == 0) {
            qs[row0 + rrow] = dq + __ldg(&scal2[0]);
            ks[row0 + rrow] = dk + __ldg(&scal2[1]);
        }
    }

    // ---- main loop
    float acc[8][2];
    #pragma unroll
    for (int rr = 0; rr < 8; rr++) { acc[rr][0] = 0.f; acc[rr][1] = 0.f; }
    const float* Abase = As + wrp*8*KPp;

    #pragma unroll 4
    for (int kb = 0; kb < KPp; kb += 4) {
        float2 w0 = *(const float2*)&Ws[(kb+0)*64 + tx*2];
        float2 w1 = *(const float2*)&Ws[(kb+1)*64 + tx*2];
        float2 w2 = *(const float2*)&Ws[(kb+2)*64 + tx*2];
        float2 w3 = *(const float2*)&Ws[(kb+3)*64 + tx*2];
        #pragma unroll
        for (int rr = 0; rr < 8; rr++) {
            float4 a = *(const float4*)&Abase[rr*KPp + kb];
            acc[rr][0] = fmaf(a.x,w0.x,fmaf(a.y,w1.x,fmaf(a.z,w2.x,fmaf(a.w,w3.x,acc[rr][0]))));
            acc[rr][1] = fmaf(a.x,w0.y,fmaf(a.y,w1.y,fmaf(a.z,w2.y,fmaf(a.w,w3.y,acc[rr][1]))));
        }
    }

    // ---- epilogue
    int col0 = ny*64 + tx*2;
    float b0 = __ldg(&bias[col0]), b1 = __ldg(&bias[col0+1]);
    float gmv = (MODE == 2) ? __ldg(gammaPtr) : 0.f;

    #pragma unroll
    for (int rr = 0; rr < 8; rr++) {
        int row = row0 + wrp*8 + rr;
        float v0 = acc[rr][0] + b0;
        float v1 = acc[rr][1] + b1;
        if (MODE == 1) {
            float2 ad = *(const float2*)&Add[(size_t)row*128 + col0];
            v0 += ad.x; v1 += ad.y;
        }
        if (MODE == 2) {
            float2 rs = *(const float2*)&Res[(size_t)row*128 + col0];
            v0 = fmaf(gmv, v0, rs.x); v1 = fmaf(gmv, v1, rs.y);
        }
        *(float2*)&C[(size_t)row*128 + col0] = make_float2(v0, v1);
    }
}

// ================= attention: one CTA (128 thr) per point, no h1 cache =================
__global__ void __launch_bounds__(128) attn2(
    const float* __restrict__ Wp1, const float* __restrict__ bp1,
    const float* __restrict__ w2, const float* __restrict__ scal)
{
    __shared__ float4 relq[KNBR];
    __shared__ int    ids[KNBR];
    __shared__ float4 s4[DDIM];
    __shared__ float  w2s[DDIM];
    __shared__ float  red[8];

    int p = blockIdx.x, tid = threadIdx.x, lane = tid & 31, wid = tid >> 5;

    float wx = __ldg(&Wp1[tid]), wy = __ldg(&Wp1[128+tid]),
          wz = __ldg(&Wp1[256+tid]), b0 = __ldg(&bp1[tid]);
    s4[tid]  = make_float4(wx, wy, wz, b0);
    w2s[tid] = __ldg(&w2[tid]);

    size_t base = (size_t)p * KNBR + tid;
    float4 rq = g_rel4[base];
    int gm = g_idx[base];
    ids[tid] = gm;
    __syncthreads();

    // phase 1: logit for neighbor tid
    float dot = 0.f;
    #pragma unroll 8
    for (int d = 0; d < DDIM; d++) {
        float4 w = s4[d];
        float h = fmaf(rq.x, w.x, fmaf(rq.y, w.y, fmaf(rq.z, w.z, w.w)));
        dot = fmaf(fmaxf(h, 0.f), w2s[d], dot);
    }
    float logit = g_qs[p] - g_ks[gm] + dot + __ldg(&scal[2]);

    // phase 2: softmax over 128
    float mx = logit;
    #pragma unroll
    for (int o = 16; o; o >>= 1) mx = fmaxf(mx, __shfl_xor_sync(0xffffffffu, mx, o));
    if (!lane) red[wid] = mx;
    __syncthreads();
    mx = fmaxf(fmaxf(red[0], red[1]), fmaxf(red[2], red[3]));
    float e = expf(logit - mx);
    float ss = e;
    #pragma unroll
    for (int o = 16; o; o >>= 1) ss += __shfl_xor_sync(0xffffffffu, ss, o);
    if (!lane) red[4 + wid] = ss;
    __syncthreads();
    ss = red[4] + red[5] + red[6] + red[7];
    rq.w = e / ss;
    relq[tid] = rq;
    __syncthreads();

    // phase 3: thread d aggregates over k (recompute pe component d)
    float accv = 0.f, acch = 0.f;
    const float* vcol = g_v + tid;
    #pragma unroll 8
    for (int k = 0; k < KNBR; k++) {
        float4 rk = relq[k];
        float h = fmaxf(fmaf(rk.x, wx, fmaf(rk.y, wy, fmaf(rk.z, wz, b0))), 0.f);
        acch = fmaf(rk.w, h, acch);
        accv = fmaf(rk.w, __ldg(&vcol[(size_t)ids[k] * DDIM]), accv);
    }
    g_aggv[(size_t)p*DDIM + tid] = accv;
    g_aggh[(size_t)p*DDIM + tid] = acch;
}

// ================= timestep embedding MLP =================
__global__ void temb_kernel(const int* __restrict__ t,
                            const float* __restrict__ tW1, const float* __restrict__ tb1,
                            const float* __restrict__ tW2, const float* __restrict__ tb2) {
    __shared__ float emb[128], h1[128];
    int b = blockIdx.x, d = threadIdx.x;
    float tv = (float)t[b];
    if (d < 64) {
        float f = expf(-logf(10000.f) * (float)d / 63.f);
        float arg = tv * f;
        emb[d] = sinf(arg);
        emb[d + 64] = cosf(arg);
    }
    __syncthreads();
    float a = tb1[d];
    for (int i = 0; i < 128; i++) a = fmaf(emb[i], tW1[i*128 + d], a);
    h1[d] = fmaxf(a, 0.f);
    __syncthreads();
    float c = tb2[d];
    for (int i = 0; i < 128; i++) c = fmaf(h1[i], tW2[i*128 + d], c);
    g_temb[b*128 + d] = c;
}

// ================= concat [x_t | fused | temb] -> g_h [P,259] =================
__global__ void concat_kernel(const float* __restrict__ x_t, const float* __restrict__ fused) {
    int p = blockIdx.x;
    int b = p >> 11;
    for (int c = threadIdx.x; c < HCAT; c += blockDim.x) {
        float v;
        if (c < 3)        v = x_t[(size_t)p*3 + c];
        else if (c < 131) v = fused[(size_t)p*DDIM + (c - 3)];
        else              v = g_temb[b*DDIM + (c - 131)];
        g_h[(size_t)p*HCAT + c] = v;
    }
}

// ================= final: LN + ReLU on raw2, then @ W3 -> 3 dims (warp/point) ==========
__global__ void out_kernel(const float* __restrict__ g2, const float* __restrict__ be2,
                           const float* __restrict__ W3, const float* __restrict__ b3,
                           float* __restrict__ out) {
    int p = blockIdx.x * 8 + (threadIdx.x >> 5);
    int lane = threadIdx.x & 31;
    float4 f = ((const float4*)(g_h2 + (size_t)p * DDIM))[lane];
    float s = f.x + f.y + f.z + f.w;
    #pragma unroll
    for (int o = 16; o; o >>= 1) s += __shfl_xor_sync(0xffffffffu, s, o);
    float mean = s * 0.0078125f;
    float d0 = f.x-mean, d1 = f.y-mean, d2 = f.z-mean, d3 = f.w-mean;
    float q = d0*d0 + d1*d1 + d2*d2 + d3*d3;
    #pragma unroll
    for (int o = 16; o; o >>= 1) q += __shfl_xor_sync(0xffffffffu, q, o);
    float rstd = rsqrtf(q * 0.0078125f + 1e-5f);
    int i0 = lane * 4;
    float4 gg = *(const float4*)&g2[i0];
    float4 bb = *(const float4*)&be2[i0];
    float v0 = fmaxf(fmaf(d0*rstd, gg.x, bb.x), 0.f);
    float v1 = fmaxf(fmaf(d1*rstd, gg.y, bb.y), 0.f);
    float v2 = fmaxf(fmaf(d2*rstd, gg.z, bb.z), 0.f);
    float v3 = fmaxf(fmaf(d3*rstd, gg.w, bb.w), 0.f);
    float a0 = v0*W3[i0*3+0] + v1*W3[(i0+1)*3+0] + v2*W3[(i0+2)*3+0] + v3*W3[(i0+3)*3+0];
    float a1 = v0*W3[i0*3+1] + v1*W3[(i0+1)*3+1] + v2*W3[(i0+2)*3+1] + v3*W3[(i0+3)*3+1];
    float a2 = v0*W3[i0*3+2] + v1*W3[(i0+1)*3+2] + v2*W3[(i0+2)*3+2] + v3*W3[(i0+3)*3+2];
    #pragma unroll
    for (int o = 16; o; o >>= 1) {
        a0 += __shfl_xor_sync(0xffffffffu, a0, o);
        a1 += __shfl_xor_sync(0xffffffffu, a1, o);
        a2 += __shfl_xor_sync(0xffffffffu, a2, o);
    }
    if (!lane) {
        out[p*3+0] = a0 + b3[0];
        out[p*3+1] = a1 + b3[1];
        out[p*3+2] = a2 + b3[2];
    }
}

#define KPP128 132
#define KPP259 260
#define GS(KPp) ((32*(KPp) + (KPp)*64) * 4)

extern "C" void kernel_launch(void* const* d_in, const int* in_sizes, int n_in,
                              void* d_out, int out_size) {
    const float* xyz   = (const float*)d_in[0];
    const float* feat  = (const float*)d_in[1];
    const float* x_t   = (const float*)d_in[2];
    const int*   t     = (const int*)  d_in[3];
    const float* Wq    = (const float*)d_in[4];
    const float* bq    = (const float*)d_in[5];
    const float* Wk    = (const float*)d_in[6];
    const float* bk    = (const float*)d_in[7];
    const float* Wv    = (const float*)d_in[8];
    const float* bv    = (const float*)d_in[9];
    const float* Wp1   = (const float*)d_in[10];
    const float* bp1   = (const float*)d_in[11];
    const float* Wp2   = (const float*)d_in[12];
    const float* bp2   = (const float*)d_in[13];
    const float* gamma = (const float*)d_in[14];
    const float* Wproj = (const float*)d_in[15];
    const float* bproj = (const float*)d_in[16];
    const float* tW1   = (const float*)d_in[17];
    const float* tb1   = (const float*)d_in[18];
    const float* tW2   = (const float*)d_in[19];
    const float* tb2   = (const float*)d_in[20];
    const float* nW1   = (const float*)d_in[21];
    const float* nb1   = (const float*)d_in[22];
    const float* ng1   = (const float*)d_in[23];
    const float* nbe1  = (const float*)d_in[24];
    const float* nW2   = (const float*)d_in[25];
    const float* nb2   = (const float*)d_in[26];
    const float* ng2   = (const float*)d_in[27];
    const float* nbe2  = (const float*)d_in[28];
    const float* nW3   = (const float*)d_in[29];
    const float* nb3   = (const float*)d_in[30];

    cudaFuncSetAttribute(gemm_k<0,false>, cudaFuncAttributeMaxDynamicSharedMemorySize, GS(KPP259));
    cudaFuncSetAttribute(gemm_k<1,false>, cudaFuncAttributeMaxDynamicSharedMemorySize, GS(KPP128));
    cudaFuncSetAttribute(gemm_k<2,false>, cudaFuncAttributeMaxDynamicSharedMemorySize, GS(KPP128));
    cudaFuncSetAttribute(gemm_k<0,true>,  cudaFuncAttributeMaxDynamicSharedMemorySize, GS(KPP128));

    float *pv, *paggv, *paggh, *pt1, *pfA, *pfB, *ph, *ph1, *ph2, *pqs, *pks;
    float *pwq, *pwk, *pw2, *psc;
    cudaGetSymbolAddress((void**)&pv,    g_v);
    cudaGetSymbolAddress((void**)&paggv, g_aggv);
    cudaGetSymbolAddress((void**)&paggh, g_aggh);
    cudaGetSymbolAddress((void**)&pt1,   g_t1);
    cudaGetSymbolAddress((void**)&pfA,   g_fA);
    cudaGetSymbolAddress((void**)&pfB,   g_fB);
    cudaGetSymbolAddress((void**)&ph,    g_h);
    cudaGetSymbolAddress((void**)&ph1,   g_h1);
    cudaGetSymbolAddress((void**)&ph2,   g_h2);
    cudaGetSymbolAddress((void**)&pqs,   g_qs);
    cudaGetSymbolAddress((void**)&pks,   g_ks);
    cudaGetSymbolAddress((void**)&pwq,   g_wqcs);
    cudaGetSymbolAddress((void**)&pwk,   g_wkcs);
    cudaGetSymbolAddress((void**)&pw2,   g_w2cs);
    cudaGetSymbolAddress((void**)&psc,   g_scal);

    knn_kernel<<<PP, 256>>>(xyz);
    prep_all<<<dim3(NLAYER,4), 128>>>(Wq, bq, Wk, bk, Wp2, bp2);

    dim3 ggrid(PP/32, 2);
    const float* cur = feat;
    float* bufs[2] = { pfA, pfB };
    for (int l = 0; l < NLAYER; l++) {
        // v = cur@Wv + bv ; fused qs/ks
        gemm_k<0,false><<<ggrid, 128, GS(KPP128)>>>(cur, 128, KPP128,
            Wv + (size_t)l*DDIM*DDIM, bv + l*DDIM, pv,
            nullptr, nullptr, nullptr, nullptr, nullptr,
            pwq + l*DDIM, pwk + l*DDIM, psc + l*4, pqs, pks);
        attn2<<<PP, 128>>>(Wp1 + (size_t)l*3*DDIM, bp1 + l*DDIM,
                           pw2 + l*DDIM, psc + l*4);
        // t1 = aggh@Wp2 + bp2 + aggv
        gemm_k<1,false><<<ggrid, 128, GS(KPP128)>>>(paggh, 128, KPP128,
            Wp2 + (size_t)l*DDIM*DDIM, bp2 + l*DDIM, pt1,
            paggv, nullptr, nullptr, nullptr, nullptr,
            nullptr, nullptr, nullptr, nullptr, nullptr);
        // nxt = cur + gamma * (t1@Wproj + bproj)
        float* nxt = bufs[l & 1];
        gemm_k<2,false><<<ggrid, 128, GS(KPP128)>>>(pt1, 128, KPP128,
            Wproj + (size_t)l*DDIM*DDIM, bproj + l*DDIM, nxt,
            nullptr, cur, gamma + l, nullptr, nullptr,
            nullptr, nullptr, nullptr, nullptr, nullptr);
        cur = nxt;
    }

    temb_kernel<<<BB, 128>>>(t, tW1, tb1, tW2, tb2);
    concat_kernel<<<PP, 128>>>(x_t, cur);
    // raw1 = h@nW1 + nb1
    gemm_k<0,false><<<ggrid, 128, GS(KPP259)>>>(ph, HCAT, KPP259,
        nW1, nb1, ph1,
        nullptr, nullptr, nullptr, nullptr, nullptr,
        nullptr, nullptr, nullptr, nullptr, nullptr);
    // raw2 = relu(LN(raw1)*g1+b1) @ nW2 + nb2   (LN fused into A-load)
    gemm_k<0,true><<<ggrid, 128, GS(KPP128)>>>(ph1, 128, KPP128,
        nW2, nb2, ph2,
        nullptr, nullptr, nullptr, ng1, nbe1,
        nullptr, nullptr, nullptr, nullptr, nullptr);
    // out = relu(LN(raw2)*g2+b2) @ nW3 + nb3
    out_kernel<<<PP/8, 256>>>(ng2, nbe2, nW3, nb3, (float*)d_out);
}

// round 3
// speedup vs baseline: 1.5772x; 1.2725x over previous
#include <cuda_runtime.h>
#include <math.h>

#define BB 2
#define NN 2048
#define DDIM 128
#define KNBR 128
#define NLAYER 4
#define PP (BB*NN)          // 4096 points
#define HCAT 259            // 3 + 128 + 128

typedef unsigned long long ull;

__device__ __forceinline__ ull pk2(float lo, float hi) {
    ull r; asm("mov.b64 %0, {%1, %2};" : "=l"(r) : "f"(lo), "f"(hi)); return r;
}
__device__ __forceinline__ float2 upk2(ull v) {
    float2 r; asm("mov.b64 {%0, %1}, %2;" : "=f"(r.x), "=f"(r.y) : "l"(v)); return r;
}
__device__ __forceinline__ void ffma2(ull& d, ull a, ull b) {
    asm("fma.rn.f32x2 %0, %1, %2, %0;" : "+l"(d) : "l"(a), "l"(b));
}

// ---------------- scratch (device globals) ----------------
__device__ int    g_idx[PP*KNBR];
__device__ float4 g_rel4[PP*KNBR];
__device__ float  g_v[PP*DDIM];
__device__ float  g_qs[PP];
__device__ float  g_ks[PP];
__device__ float  g_aggv[PP*DDIM];
__device__ float  g_aggh[PP*DDIM];
__device__ float  g_t1[PP*DDIM];
__device__ float  g_fA[PP*DDIM];
__device__ float  g_fB[PP*DDIM];
__device__ float  g_wqcs[NLAYER*DDIM];
__device__ float  g_wkcs[NLAYER*DDIM];
__device__ float  g_w2cs[NLAYER*DDIM];
__device__ float  g_scal[NLAYER*4];
__device__ float  g_temb[BB*DDIM];
__device__ float  g_h[PP*HCAT];
__device__ float  g_h1[PP*DDIM];
__device__ float  g_h2[PP*DDIM];

// ================= KNN (unchanged) =================
__global__ void knn_kernel(const float* __restrict__ xyz) {
    __shared__ float xs[NN*3];
    __shared__ float dsh[NN];
    __shared__ int   red[8];
    __shared__ int   slot;

    int p = blockIdx.x;
    int b = p >> 11;
    int n = p & 2047;
    int tid  = threadIdx.x;
    int lane = tid & 31, wid = tid >> 5;

    const float4* X4 = (const float4*)(xyz + (size_t)b * NN * 3);
    float4* xs4 = (float4*)xs;
    #pragma unroll
    for (int i = tid; i < (NN*3)/4; i += 256) xs4[i] = X4[i];
    __syncthreads();

    float x0 = xs[n*3+0], y0 = xs[n*3+1], z0 = xs[n*3+2];
    float sq0 = x0*x0 + y0*y0 + z0*z0;

    unsigned ul[8];
    #pragma unroll
    for (int i = 0; i < 8; i++) {
        int m = tid + (i << 8);
        float xm = xs[m*3+0], ym = xs[m*3+1], zm = xs[m*3+2];
        float sqm = xm*xm + ym*ym + zm*zm;
        float dot = x0*xm + y0*ym + z0*zm;
        float d = sq0 + sqm - 2.0f*dot;
        dsh[m] = d;
        unsigned u = __float_as_uint(d);
        ul[i] = (u & 0x80000000u) ? ~u : (u | 0x80000000u);
    }
    __syncthreads();

    unsigned lo = 0u, hi = 0xFFFFFFFFu;
    while (lo < hi) {
        unsigned mid = lo + ((hi - lo) >> 1);
        int c = 0;
        #pragma unroll
        for (int i = 0; i < 8; i++) c += (ul[i] <= mid);
        #pragma unroll
        for (int o = 16; o; o >>= 1) c += __shfl_xor_sync(0xffffffffu, c, o);
        if (!lane) red[wid] = c;
        __syncthreads();
        int tot = red[0]+red[1]+red[2]+red[3]+red[4]+red[5]+red[6]+red[7];
        if (tot >= KNBR) hi = mid; else lo = mid + 1;
        __syncthreads();
    }
    unsigned ustar = lo;

    int c2 = 0;
    #pragma unroll
    for (int i = 0; i < 8; i++) c2 += (ul[i] < ustar);
    #pragma unroll
    for (int o = 16; o; o >>= 1) c2 += __shfl_xor_sync(0xffffffffu, c2, o);
    if (!lane) red[wid] = c2;
    __syncthreads();
    int c_lt = red[0]+red[1]+red[2]+red[3]+red[4]+red[5]+red[6]+red[7];
    int r = KNBR - c_lt;

    if (tid == 0) slot = 0;
    __syncthreads();

    #pragma unroll
    for (int i = 0; i < 8; i++) {
        int m = tid + (i << 8);
        bool sel = false;
        if (ul[i] < ustar) sel = true;
        else if (ul[i] == ustar && r > 0) {
            unsigned mybits = __float_as_uint(dsh[m]);
            int rk = 0;
            for (int mm = 0; mm < m; ++mm)
                rk += (__float_as_uint(dsh[mm]) == mybits);
            if (rk < r) sel = true;
        }
        if (sel) {
            int s = atomicAdd(&slot, 1);
            size_t o = (size_t)p * KNBR + s;
            g_idx[o] = b * NN + m;
            g_rel4[o] = make_float4(x0 - xs[m*3+0], y0 - xs[m*3+1], z0 - xs[m*3+2], 0.f);
        }
    }
}

// ================= prep for ALL layers (unchanged) =================
__global__ void prep_all(const float* __restrict__ Wq, const float* __restrict__ bq,
                         const float* __restrict__ Wk, const float* __restrict__ bk,
                         const float* __restrict__ Wp2, const float* __restrict__ bp2) {
    int l = blockIdx.x, kind = blockIdx.y, tid = threadIdx.x;
    if (kind < 3) {
        const float* W = (kind == 0 ? Wq : kind == 1 ? Wk : Wp2) + (size_t)l * DDIM * DDIM;
        float* dst = (kind == 0 ? g_wqcs : kind == 1 ? g_wkcs : g_w2cs) + l * DDIM;
        int seg = tid & 3;
        int rbase = tid >> 2;
        for (int rr = 0; rr < DDIM; rr += 32) {
            int rrow = rbase + rr;
            const float4* row = (const float4*)(W + (size_t)rrow * DDIM + seg * 32);
            float s = 0.f;
            #pragma unroll
            for (int j = 0; j < 8; j++) { float4 v = row[j]; s += v.x + v.y + v.z + v.w; }
            s += __shfl_xor_sync(0xffffffffu, s, 1);
            s += __shfl_xor_sync(0xffffffffu, s, 2);
            if (seg == 0) dst[rrow] = s;
        }
    } else {
        int w = tid >> 5, lane = tid & 31;
        if (w < 3) {
            const float* bb = (w == 0 ? bq : w == 1 ? bk : bp2) + l * DDIM;
            float s = bb[lane] + bb[lane+32] + bb[lane+64] + bb[lane+96];
            #pragma unroll
            for (int o = 16; o; o >>= 1) s += __shfl_xor_sync(0xffffffffu, s, o);
            if (!lane) g_scal[l*4 + w] = s;
        }
    }
}

// ================= GEMM v3: f32x2 packed, transposed W, BM=16 =================
// 128 threads. grid (M/16, 2); blockIdx.y = 64-col half.
// warp -> 4 rows; lane -> local cols {tx, tx+32}. acc = (even-k, odd-k) pairs.
// MODE: 0 = +bias (opt fused qs/ks), 1 = +bias+Add, 2 = Res + gamma*(acc+bias)
// LNA: LayerNorm+ReLU applied to A rows in smem (K must be 128)
template<int MODE, bool LNA>
__global__ void __launch_bounds__(128) gemm_v3(
    const float* __restrict__ A, int K, int KPp,
    const float* __restrict__ W,
    const float* __restrict__ bias,
    float* __restrict__ C,
    const float* __restrict__ Add,
    const float* __restrict__ Res,
    const float* __restrict__ gammaPtr,
    const float* __restrict__ lng, const float* __restrict__ lnb,
    const float* __restrict__ wq, const float* __restrict__ wk,
    const float* __restrict__ scal2,
    float* __restrict__ qs, float* __restrict__ ks)
{
    extern __shared__ float sm[];
    float* As = sm;                 // 16 * KPp
    float* Wt = sm + 16 * KPp;      // 64 * KPp  (Wt[c*KPp + k])

    int tid = threadIdx.x, tx = tid & 31, wrp = tid >> 5;
    int row0 = blockIdx.x * 16, ny = blockIdx.y;

    // ---- A tile
    if ((K & 3) == 0) {
        int K4 = K >> 2, KP4 = KPp >> 2;
        const float4* A4 = (const float4*)A;
        float4* As4 = (float4*)As;
        for (int i = tid; i < 16*KP4; i += 128) {
            int rr = i / KP4, c = i - rr*KP4;
            As4[i] = (c < K4) ? A4[(size_t)(row0+rr)*K4 + c] : make_float4(0.f,0.f,0.f,0.f);
        }
    } else {
        for (int i = tid; i < 16*KPp; i += 128) {
            int rr = i / KPp, c = i - rr*KPp;
            As[i] = (c < K) ? A[(size_t)(row0+rr)*K + c] : 0.f;
        }
    }

    // ---- W half, transposed into Wt[c][k]
    {
        int nblk = 16 * KPp;            // 64 cols * KPp/4 k-blocks
        for (int i = tid; i < nblk; i += 128) {
            int c = i & 63, kb4 = i >> 6;
            int k0 = kb4 << 2;
            float w0 = (k0+0 < K) ? W[(size_t)(k0+0)*128 + ny*64 + c] : 0.f;
            float w1 = (k0+1 < K) ? W[(size_t)(k0+1)*128 + ny*64 + c] : 0.f;
            float w2 = (k0+2 < K) ? W[(size_t)(k0+2)*128 + ny*64 + c] : 0.f;
            float w3 = (k0+3 < K) ? W[(size_t)(k0+3)*128 + ny*64 + c] : 0.f;
            *(float4*)&Wt[c*KPp + k0] = make_float4(w0, w1, w2, w3);
        }
    }
    __syncthreads();

    // ---- optional LN+ReLU on A rows (K==128)
    if (LNA) {
        int rrow = tid >> 3, seg = tid & 7;
        float* rowp = As + rrow*KPp + seg*16;
        float s = 0.f;
        #pragma unroll
        for (int j = 0; j < 16; j++) s += rowp[j];
        s += __shfl_xor_sync(0xffffffffu, s, 1);
        s += __shfl_xor_sync(0xffffffffu, s, 2);
        s += __shfl_xor_sync(0xffffffffu, s, 4);
        float mean = s * 0.0078125f;
        float q = 0.f;
        #pragma unroll
        for (int j = 0; j < 16; j++) { float d = rowp[j] - mean; q = fmaf(d, d, q); }
        q += __shfl_xor_sync(0xffffffffu, q, 1);
        q += __shfl_xor_sync(0xffffffffu, q, 2);
        q += __shfl_xor_sync(0xffffffffu, q, 4);
        float rstd = rsqrtf(q * 0.0078125f + 1e-5f);
        #pragma unroll
        for (int j = 0; j < 16; j++) {
            int c = seg*16 + j;
            rowp[j] = fmaxf(fmaf((rowp[j]-mean)*rstd, __ldg(&lng[c]), __ldg(&lnb[c])), 0.f);
        }
        __syncthreads();
    }

    // ---- fused qs/ks (v-gemm, half 0)
    if (MODE == 0 && qs != nullptr && ny == 0) {
        int rrow = tid >> 3, seg = tid & 7;
        const float* rowp = As + rrow*KPp + seg*16;
        float dq = 0.f, dk = 0.f;
        #pragma unroll
        for (int j = 0; j < 16; j++) {
            float a = rowp[j];
            dq = fmaf(a, __ldg(&wq[seg*16+j]), dq);
            dk = fmaf(a, __ldg(&wk[seg*16+j]), dk);
        }
        dq += __shfl_xor_sync(0xffffffffu, dq, 1);
        dq += __shfl_xor_sync(0xffffffffu, dq, 2);
        dq += __shfl_xor_sync(0xffffffffu, dq, 4);
        dk += __shfl_xor_sync(0xffffffffu, dk, 1);
        dk += __shfl_xor_sync(0xffffffffu, dk, 2);
        dk += __shfl_xor_sync(0xffffffffu, dk, 4);
        if (seg == 0) {
            qs[row0 + rrow] = dq + __ldg(&scal2[0]);
            ks[row0 + rrow] = dk + __ldg(&scal2[1]);
        }
    }

    // ---- main loop (packed pairs, no pack MOV needed on operands)
    ull acc[4][2];
    #pragma unroll
    for (int rr = 0; rr < 4; rr++) { acc[rr][0] = pk2(0.f, 0.f); acc[rr][1] = pk2(0.f, 0.f); }

    const float* a0 = As + (wrp*4+0)*KPp;
    const float* a1 = As + (wrp*4+1)*KPp;
    const float* a2 = As + (wrp*4+2)*KPp;
    const float* a3 = As + (wrp*4+3)*KPp;
    const float* w0p = Wt + tx*KPp;
    const float* w1p = Wt + (tx+32)*KPp;

    #pragma unroll 4
    for (int kb = 0; kb < KPp; kb += 4) {
        float4 wa = *(const float4*)&w0p[kb];
        float4 wb = *(const float4*)&w1p[kb];
        ull waL = pk2(wa.x, wa.y), waH = pk2(wa.z, wa.w);
        ull wbL = pk2(wb.x, wb.y), wbH = pk2(wb.z, wb.w);
        float4 v0 = *(const float4*)&a0[kb];
        float4 v1 = *(const float4*)&a1[kb];
        float4 v2 = *(const float4*)&a2[kb];
        float4 v3 = *(const float4*)&a3[kb];
        ull p0L = pk2(v0.x, v0.y), p0H = pk2(v0.z, v0.w);
        ull p1L = pk2(v1.x, v1.y), p1H = pk2(v1.z, v1.w);
        ull p2L = pk2(v2.x, v2.y), p2H = pk2(v2.z, v2.w);
        ull p3L = pk2(v3.x, v3.y), p3H = pk2(v3.z, v3.w);
        ffma2(acc[0][0], p0L, waL); ffma2(acc[0][0], p0H, waH);
        ffma2(acc[1][0], p1L, waL); ffma2(acc[1][0], p1H, waH);
        ffma2(acc[2][0], p2L, waL); ffma2(acc[2][0], p2H, waH);
        ffma2(acc[3][0], p3L, waL); ffma2(acc[3][0], p3H, waH);
        ffma2(acc[0][1], p0L, wbL); ffma2(acc[0][1], p0H, wbH);
        ffma2(acc[1][1], p1L, wbL); ffma2(acc[1][1], p1H, wbH);
        ffma2(acc[2][1], p2L, wbL); ffma2(acc[2][1], p2H, wbH);
        ffma2(acc[3][1], p3L, wbL); ffma2(acc[3][1], p3H, wbH);
    }

    // ---- epilogue
    int c0 = ny*64 + tx, c1 = c0 + 32;
    float b0 = __ldg(&bias[c0]), b1 = __ldg(&bias[c1]);
    float gmv = (MODE == 2) ? __ldg(gammaPtr) : 0.f;

    #pragma unroll
    for (int rr = 0; rr < 4; rr++) {
        int row = row0 + wrp*4 + rr;
        float2 s0 = upk2(acc[rr][0]);
        float2 s1 = upk2(acc[rr][1]);
        float v0 = s0.x + s0.y + b0;
        float v1 = s1.x + s1.y + b1;
        if (MODE == 1) {
            v0 += Add[(size_t)row*128 + c0];
            v1 += Add[(size_t)row*128 + c1];
        }
        if (MODE == 2) {
            v0 = fmaf(gmv, v0, Res[(size_t)row*128 + c0]);
            v1 = fmaf(gmv, v1, Res[(size_t)row*128 + c1]);
        }
        C[(size_t)row*128 + c0] = v0;
        C[(size_t)row*128 + c1] = v1;
    }
}

// ================= attention v3: warp-per-k-slice aggregation =================
__global__ void __launch_bounds__(128) attn3(
    const float* __restrict__ Wp1, const float* __restrict__ bp1,
    const float* __restrict__ w2, const float* __restrict__ scal)
{
    __shared__ float4 relq[KNBR];
    __shared__ int    ids[KNBR];
    __shared__ float4 s4[DDIM];
    __shared__ float  w2s[DDIM];
    __shared__ float  red[8];
    __shared__ float  rv[4*DDIM];    // per-warp partial aggv
    __shared__ float  rh[4*DDIM];    // per-warp partial aggh

    int p = blockIdx.x, tid = threadIdx.x, lane = tid & 31, wrp = tid >> 5;

    s4[tid]  = make_float4(__ldg(&Wp1[tid]), __ldg(&Wp1[128+tid]),
                           __ldg(&Wp1[256+tid]), __ldg(&bp1[tid]));
    w2s[tid] = __ldg(&w2[tid]);

    size_t base = (size_t)p * KNBR + tid;
    float4 rq = g_rel4[base];
    int gm = g_idx[base];
    ids[tid] = gm;
    __syncthreads();

    // ---- phase 1: logit for neighbor tid
    float dot = 0.f;
    #pragma unroll 8
    for (int d = 0; d < DDIM; d++) {
        float4 w = s4[d];
        float h = fmaf(rq.x, w.x, fmaf(rq.y, w.y, fmaf(rq.z, w.z, w.w)));
        dot = fmaf(fmaxf(h, 0.f), w2s[d], dot);
    }
    float logit = g_qs[p] - g_ks[gm] + dot + __ldg(&scal[2]);

    // ---- phase 2: softmax over 128
    float mx = logit;
    #pragma unroll
    for (int o = 16; o; o >>= 1) mx = fmaxf(mx, __shfl_xor_sync(0xffffffffu, mx, o));
    if (!lane) red[wrp] = mx;
    __syncthreads();
    mx = fmaxf(fmaxf(red[0], red[1]), fmaxf(red[2], red[3]));
    float e = expf(logit - mx);
    float ss = e;
    #pragma unroll
    for (int o = 16; o; o >>= 1) ss += __shfl_xor_sync(0xffffffffu, ss, o);
    if (!lane) red[4 + wrp] = ss;
    __syncthreads();
    ss = red[4] + red[5] + red[6] + red[7];
    rq.w = e / ss;
    relq[tid] = rq;
    __syncthreads();

    // ---- phase 3: warp wrp handles k in [wrp*32, wrp*32+32); lane -> 4 cols
    float wxr[4], wyr[4], wzr[4], br[4];
    #pragma unroll
    for (int j = 0; j < 4; j++) {
        float4 t = s4[lane*4 + j];
        wxr[j] = t.x; wyr[j] = t.y; wzr[j] = t.z; br[j] = t.w;
    }
    float av0=0.f, av1=0.f, av2=0.f, av3=0.f;
    float ah0=0.f, ah1=0.f, ah2=0.f, ah3=0.f;
    int kbase = wrp * 32;
    #pragma unroll 4
    for (int j = 0; j < 32; j++) {
        float4 rk = relq[kbase + j];
        int id = ids[kbase + j];
        float4 v = *(const float4*)&g_v[(size_t)id * DDIM + lane*4];
        float a = rk.w;
        float h0 = fmaxf(fmaf(rk.x,wxr[0],fmaf(rk.y,wyr[0],fmaf(rk.z,wzr[0],br[0]))), 0.f);
        float h1 = fmaxf(fmaf(rk.x,wxr[1],fmaf(rk.y,wyr[1],fmaf(rk.z,wzr[1],br[1]))), 0.f);
        float h2 = fmaxf(fmaf(rk.x,wxr[2],fmaf(rk.y,wyr[2],fmaf(rk.z,wzr[2],br[2]))), 0.f);
        float h3 = fmaxf(fmaf(rk.x,wxr[3],fmaf(rk.y,wyr[3],fmaf(rk.z,wzr[3],br[3]))), 0.f);
        ah0 = fmaf(a, h0, ah0); ah1 = fmaf(a, h1, ah1);
        ah2 = fmaf(a, h2, ah2); ah3 = fmaf(a, h3, ah3);
        av0 = fmaf(a, v.x, av0); av1 = fmaf(a, v.y, av1);
        av2 = fmaf(a, v.z, av2); av3 = fmaf(a, v.w, av3);
    }
    *(float4*)&rv[wrp*DDIM + lane*4] = make_float4(av0, av1, av2, av3);
    *(float4*)&rh[wrp*DDIM + lane*4] = make_float4(ah0, ah1, ah2, ah3);
    __syncthreads();

    float sv = rv[tid] + rv[DDIM+tid] + rv[2*DDIM+tid] + rv[3*DDIM+tid];
    float sh = rh[tid] + rh[DDIM+tid] + rh[2*DDIM+tid] + rh[3*DDIM+tid];
    g_aggv[(size_t)p*DDIM + tid] = sv;
    g_aggh[(size_t)p*DDIM + tid] = sh;
}

// ================= timestep embedding MLP (unchanged) =================
__global__ void temb_kernel(const int* __restrict__ t,
                            const float* __restrict__ tW1, const float* __restrict__ tb1,
                            const float* __restrict__ tW2, const float* __restrict__ tb2) {
    __shared__ float emb[128], h1[128];
    int b = blockIdx.x, d = threadIdx.x;
    float tv = (float)t[b];
    if (d < 64) {
        float f = expf(-logf(10000.f) * (float)d / 63.f);
        float arg = tv * f;
        emb[d] = sinf(arg);
        emb[d + 64] = cosf(arg);
    }
    __syncthreads();
    float a = tb1[d];
    for (int i = 0; i < 128; i++) a = fmaf(emb[i], tW1[i*128 + d], a);
    h1[d] = fmaxf(a, 0.f);
    __syncthreads();
    float c = tb2[d];
    for (int i = 0; i < 128; i++) c = fmaf(h1[i], tW2[i*128 + d], c);
    g_temb[b*128 + d] = c;
}

// ================= concat (unchanged) =================
__global__ void concat_kernel(const float* __restrict__ x_t, const float* __restrict__ fused) {
    int p = blockIdx.x;
    int b = p >> 11;
    for (int c = threadIdx.x; c < HCAT; c += blockDim.x) {
        float v;
        if (c < 3)        v = x_t[(size_t)p*3 + c];
        else if (c < 131) v = fused[(size_t)p*DDIM + (c - 3)];
        else              v = g_temb[b*DDIM + (c - 131)];
        g_h[(size_t)p*HCAT + c] = v;
    }
}

// ================= final LN+ReLU+proj (unchanged) =================
__global__ void out_kernel(const float* __restrict__ g2, const float* __restrict__ be2,
                           const float* __restrict__ W3, const float* __restrict__ b3,
                           float* __restrict__ out) {
    int p = blockIdx.x * 8 + (threadIdx.x >> 5);
    int lane = threadIdx.x & 31;
    float4 f = ((const float4*)(g_h2 + (size_t)p * DDIM))[lane];
    float s = f.x + f.y + f.z + f.w;
    #pragma unroll
    for (int o = 16; o; o >>= 1) s += __shfl_xor_sync(0xffffffffu, s, o);
    float mean = s * 0.0078125f;
    float d0 = f.x-mean, d1 = f.y-mean, d2 = f.z-mean, d3 = f.w-mean;
    float q = d0*d0 + d1*d1 + d2*d2 + d3*d3;
    #pragma unroll
    for (int o = 16; o; o >>= 1) q += __shfl_xor_sync(0xffffffffu, q, o);
    float rstd = rsqrtf(q * 0.0078125f + 1e-5f);
    int i0 = lane * 4;
    float4 gg = *(const float4*)&g2[i0];
    float4 bb = *(const float4*)&be2[i0];
    float v0 = fmaxf(fmaf(d0*rstd, gg.x, bb.x), 0.f);
    float v1 = fmaxf(fmaf(d1*rstd, gg.y, bb.y), 0.f);
    float v2 = fmaxf(fmaf(d2*rstd, gg.z, bb.z), 0.f);
    float v3 = fmaxf(fmaf(d3*rstd, gg.w, bb.w), 0.f);
    float a0 = v0*W3[i0*3+0] + v1*W3[(i0+1)*3+0] + v2*W3[(i0+2)*3+0] + v3*W3[(i0+3)*3+0];
    float a1 = v0*W3[i0*3+1] + v1*W3[(i0+1)*3+1] + v2*W3[(i0+2)*3+1] + v3*W3[(i0+3)*3+1];
    float a2 = v0*W3[i0*3+2] + v1*W3[(i0+1)*3+2] + v2*W3[(i0+2)*3+2] + v3*W3[(i0+3)*3+2];
    #pragma unroll
    for (int o = 16; o; o >>= 1) {
        a0 += __shfl_xor_sync(0xffffffffu, a0, o);
        a1 += __shfl_xor_sync(0xffffffffu, a1, o);
        a2 += __shfl_xor_sync(0xffffffffu, a2, o);
    }
    if (!lane) {
        out[p*3+0] = a0 + b3[0];
        out[p*3+1] = a1 + b3[1];
        out[p*3+2] = a2 + b3[2];
    }
}

#define KPP128 132
#define KPP259 260
#define GS(KPp) (80 * (KPp) * 4)

extern "C" void kernel_launch(void* const* d_in, const int* in_sizes, int n_in,
                              void* d_out, int out_size) {
    const float* xyz   = (const float*)d_in[0];
    const float* feat  = (const float*)d_in[1];
    const float* x_t   = (const float*)d_in[2];
    const int*   t     = (const int*)  d_in[3];
    const float* Wq    = (const float*)d_in[4];
    const float* bq    = (const float*)d_in[5];
    const float* Wk    = (const float*)d_in[6];
    const float* bk    = (const float*)d_in[7];
    const float* Wv    = (const float*)d_in[8];
    const float* bv    = (const float*)d_in[9];
    const float* Wp1   = (const float*)d_in[10];
    const float* bp1   = (const float*)d_in[11];
    const float* Wp2   = (const float*)d_in[12];
    const float* bp2   = (const float*)d_in[13];
    const float* gamma = (const float*)d_in[14];
    const float* Wproj = (const float*)d_in[15];
    const float* bproj = (const float*)d_in[16];
    const float* tW1   = (const float*)d_in[17];
    const float* tb1   = (const float*)d_in[18];
    const float* tW2   = (const float*)d_in[19];
    const float* tb2   = (const float*)d_in[20];
    const float* nW1   = (const float*)d_in[21];
    const float* nb1   = (const float*)d_in[22];
    const float* ng1   = (const float*)d_in[23];
    const float* nbe1  = (const float*)d_in[24];
    const float* nW2   = (const float*)d_in[25];
    const float* nb2   = (const float*)d_in[26];
    const float* ng2   = (const float*)d_in[27];
    const float* nbe2  = (const float*)d_in[28];
    const float* nW3   = (const float*)d_in[29];
    const float* nb3   = (const float*)d_in[30];

    cudaFuncSetAttribute(gemm_v3<0,false>, cudaFuncAttributeMaxDynamicSharedMemorySize, GS(KPP259));
    cudaFuncSetAttribute(gemm_v3<1,false>, cudaFuncAttributeMaxDynamicSharedMemorySize, GS(KPP128));
    cudaFuncSetAttribute(gemm_v3<2,false>, cudaFuncAttributeMaxDynamicSharedMemorySize, GS(KPP128));
    cudaFuncSetAttribute(gemm_v3<0,true>,  cudaFuncAttributeMaxDynamicSharedMemorySize, GS(KPP128));

    float *pv, *paggv, *paggh, *pt1, *pfA, *pfB, *ph, *ph1, *ph2, *pqs, *pks;
    float *pwq, *pwk, *pw2, *psc;
    cudaGetSymbolAddress((void**)&pv,    g_v);
    cudaGetSymbolAddress((void**)&paggv, g_aggv);
    cudaGetSymbolAddress((void**)&paggh, g_aggh);
    cudaGetSymbolAddress((void**)&pt1,   g_t1);
    cudaGetSymbolAddress((void**)&pfA,   g_fA);
    cudaGetSymbolAddress((void**)&pfB,   g_fB);
    cudaGetSymbolAddress((void**)&ph,    g_h);
    cudaGetSymbolAddress((void**)&ph1,   g_h1);
    cudaGetSymbolAddress((void**)&ph2,   g_h2);
    cudaGetSymbolAddress((void**)&pqs,   g_qs);
    cudaGetSymbolAddress((void**)&pks,   g_ks);
    cudaGetSymbolAddress((void**)&pwq,   g_wqcs);
    cudaGetSymbolAddress((void**)&pwk,   g_wkcs);
    cudaGetSymbolAddress((void**)&pw2,   g_w2cs);
    cudaGetSymbolAddress((void**)&psc,   g_scal);

    knn_kernel<<<PP, 256>>>(xyz);
    prep_all<<<dim3(NLAYER,4), 128>>>(Wq, bq, Wk, bk, Wp2, bp2);

    dim3 ggrid(PP/16, 2);
    const float* cur = feat;
    float* bufs[2] = { pfA, pfB };
    for (int l = 0; l < NLAYER; l++) {
        gemm_v3<0,false><<<ggrid, 128, GS(KPP128)>>>(cur, 128, KPP128,
            Wv + (size_t)l*DDIM*DDIM, bv + l*DDIM, pv,
            nullptr, nullptr, nullptr, nullptr, nullptr,
            pwq + l*DDIM, pwk + l*DDIM, psc + l*4, pqs, pks);
        attn3<<<PP, 128>>>(Wp1 + (size_t)l*3*DDIM, bp1 + l*DDIM,
                           pw2 + l*DDIM, psc + l*4);
        gemm_v3<1,false><<<ggrid, 128, GS(KPP128)>>>(paggh, 128, KPP128,
            Wp2 + (size_t)l*DDIM*DDIM, bp2 + l*DDIM, pt1,
            paggv, nullptr, nullptr, nullptr, nullptr,
            nullptr, nullptr, nullptr, nullptr, nullptr);
        float* nxt = bufs[l & 1];
        gemm_v3<2,false><<<ggrid, 128, GS(KPP128)>>>(pt1, 128, KPP128,
            Wproj + (size_t)l*DDIM*DDIM, bproj + l*DDIM, nxt,
            nullptr, cur, gamma + l, nullptr, nullptr,
            nullptr, nullptr, nullptr, nullptr, nullptr);
        cur = nxt;
    }

    temb_kernel<<<BB, 128>>>(t, tW1, tb1, tW2, tb2);
    concat_kernel<<<PP, 128>>>(x_t, cur);
    gemm_v3<0,false><<<ggrid, 128, GS(KPP259)>>>(ph, HCAT, KPP259,
        nW1, nb1, ph1,
        nullptr, nullptr, nullptr, nullptr, nullptr,
        nullptr, nullptr, nullptr, nullptr, nullptr);
    gemm_v3<0,true><<<ggrid, 128, GS(KPP128)>>>(ph1, 128, KPP128,
        nW2, nb2, ph2,
        nullptr, nullptr, nullptr, ng1, nbe1,
        nullptr, nullptr, nullptr, nullptr, nullptr);
    out_kernel<<<PP/8, 256>>>(ng2, nbe2, nW3, nb3, (float*)d_out);
}

// round 5
// speedup vs baseline: 1.6422x; 1.0412x over previous
#include <cuda_runtime.h>
#include <cuda_bf16.h>
#include <math.h>

#define BB 2
#define NN 2048
#define DDIM 128
#define KNBR 128
#define NLAYER 4
#define PP (BB*NN)          // 4096 points
#define HCAT 259            // 3 + 128 + 128

typedef unsigned long long ull;

__device__ __forceinline__ ull pk2(float lo, float hi) {
    ull r; asm("mov.b64 %0, {%1, %2};" : "=l"(r) : "f"(lo), "f"(hi)); return r;
}
__device__ __forceinline__ float2 upk2(ull v) {
    float2 r; asm("mov.b64 {%0, %1}, %2;" : "=f"(r.x), "=f"(r.y) : "l"(v)); return r;
}
__device__ __forceinline__ void ffma2(ull& d, ull a, ull b) {
    asm("fma.rn.f32x2 %0, %1, %2, %0;" : "+l"(d) : "l"(a), "l"(b));
}

// ---------------- scratch (device globals) ----------------
__device__ int            g_idx[PP*KNBR];
__device__ float4         g_rel4[PP*KNBR];
__device__ __nv_bfloat16  g_vh[PP*DDIM];
__device__ float          g_qs[PP];
__device__ float          g_ks[PP];
__device__ float          g_aggv[PP*DDIM];
__device__ float          g_aggh[PP*DDIM];
__device__ float          g_t1[PP*DDIM];
__device__ float          g_fA[PP*DDIM];
__device__ float          g_fB[PP*DDIM];
__device__ float          g_wqcs[NLAYER*DDIM];
__device__ float          g_wkcs[NLAYER*DDIM];
__device__ float          g_w2cs[NLAYER*DDIM];
__device__ float          g_scal[NLAYER*4];
__device__ float4         g_pe4[NLAYER*DDIM];   // w2-scaled, sign-sorted (wx,wy,wz,b)
__device__ int            g_npos[NLAYER];
__device__ float          g_temb[BB*DDIM];
__device__ float          g_h1[PP*DDIM];
__device__ float          g_h2[PP*DDIM];

// ================= KNN =================
__global__ void knn_kernel(const float* __restrict__ xyz) {
    __shared__ float xs[NN*3];
    __shared__ float dsh[NN];
    __shared__ int   red[8];
    __shared__ int   slot;

    int p = blockIdx.x;
    int b = p >> 11;
    int n = p & 2047;
    int tid  = threadIdx.x;
    int lane = tid & 31, wid = tid >> 5;

    const float4* X4 = (const float4*)(xyz + (size_t)b * NN * 3);
    float4* xs4 = (float4*)xs;
    #pragma unroll
    for (int i = tid; i < (NN*3)/4; i += 256) xs4[i] = X4[i];
    __syncthreads();

    float x0 = xs[n*3+0], y0 = xs[n*3+1], z0 = xs[n*3+2];
    float sq0 = x0*x0 + y0*y0 + z0*z0;

    unsigned ul[8];
    #pragma unroll
    for (int i = 0; i < 8; i++) {
        int m = tid + (i << 8);
        float xm = xs[m*3+0], ym = xs[m*3+1], zm = xs[m*3+2];
        float sqm = xm*xm + ym*ym + zm*zm;
        float dot = x0*xm + y0*ym + z0*zm;
        float d = sq0 + sqm - 2.0f*dot;
        dsh[m] = d;
        unsigned u = __float_as_uint(d);
        ul[i] = (u & 0x80000000u) ? ~u : (u | 0x80000000u);
    }
    __syncthreads();

    unsigned lo = 0u, hi = 0xFFFFFFFFu;
    while (lo < hi) {
        unsigned mid = lo + ((hi - lo) >> 1);
        int c = 0;
        #pragma unroll
        for (int i = 0; i < 8; i++) c += (ul[i] <= mid);
        #pragma unroll
        for (int o = 16; o; o >>= 1) c += __shfl_xor_sync(0xffffffffu, c, o);
        if (!lane) red[wid] = c;
        __syncthreads();
        int tot = red[0]+red[1]+red[2]+red[3]+red[4]+red[5]+red[6]+red[7];
        if (tot >= KNBR) hi = mid; else lo = mid + 1;
        __syncthreads();
    }
    unsigned ustar = lo;

    int c2 = 0;
    #pragma unroll
    for (int i = 0; i < 8; i++) c2 += (ul[i] < ustar);
    #pragma unroll
    for (int o = 16; o; o >>= 1) c2 += __shfl_xor_sync(0xffffffffu, c2, o);
    if (!lane) red[wid] = c2;
    __syncthreads();
    int c_lt = red[0]+red[1]+red[2]+red[3]+red[4]+red[5]+red[6]+red[7];
    int r = KNBR - c_lt;

    if (tid == 0) slot = 0;
    __syncthreads();

    #pragma unroll
    for (int i = 0; i < 8; i++) {
        int m = tid + (i << 8);
        bool sel = false;
        if (ul[i] < ustar) sel = true;
        else if (ul[i] == ustar && r > 0) {
            unsigned mybits = __float_as_uint(dsh[m]);
            int rk = 0;
            for (int mm = 0; mm < m; ++mm)
                rk += (__float_as_uint(dsh[mm]) == mybits);
            if (rk < r) sel = true;
        }
        if (sel) {
            int s = atomicAdd(&slot, 1);
            size_t o = (size_t)p * KNBR + s;
            g_idx[o] = b * NN + m;
            g_rel4[o] = make_float4(x0 - xs[m*3+0], y0 - xs[m*3+1], z0 - xs[m*3+2], 0.f);
        }
    }
}

// ================= prep for ALL layers =================
__global__ void prep_all(const float* __restrict__ Wq, const float* __restrict__ bq,
                         const float* __restrict__ Wk, const float* __restrict__ bk,
                         const float* __restrict__ Wp2, const float* __restrict__ bp2) {
    int l = blockIdx.x, kind = blockIdx.y, tid = threadIdx.x;
    if (kind < 3) {
        const float* W = (kind == 0 ? Wq : kind == 1 ? Wk : Wp2) + (size_t)l * DDIM * DDIM;
        float* dst = (kind == 0 ? g_wqcs : kind == 1 ? g_wkcs : g_w2cs) + l * DDIM;
        int seg = tid & 3;
        int rbase = tid >> 2;
        for (int rr = 0; rr < DDIM; rr += 32) {
            int rrow = rbase + rr;
            const float4* row = (const float4*)(W + (size_t)rrow * DDIM + seg * 32);
            float s = 0.f;
            #pragma unroll
            for (int j = 0; j < 8; j++) { float4 v = row[j]; s += v.x + v.y + v.z + v.w; }
            s += __shfl_xor_sync(0xffffffffu, s, 1);
            s += __shfl_xor_sync(0xffffffffu, s, 2);
            if (seg == 0) dst[rrow] = s;
        }
    } else {
        int w = tid >> 5, lane = tid & 31;
        if (w < 3) {
            const float* bb = (w == 0 ? bq : w == 1 ? bk : bp2) + l * DDIM;
            float s = bb[lane] + bb[lane+32] + bb[lane+64] + bb[lane+96];
            #pragma unroll
            for (int o = 16; o; o >>= 1) s += __shfl_xor_sync(0xffffffffu, s, o);
            if (!lane) g_scal[l*4 + w] = s;
        }
    }
}

// ================= prep2: scaled + sign-sorted pe weights =================
__global__ void prep2(const float* __restrict__ Wp1, const float* __restrict__ bp1) {
    __shared__ int cntP[4];
    int l = blockIdx.x, tid = threadIdx.x, lane = tid & 31, wid = tid >> 5;
    const float* W = Wp1 + (size_t)l * 3 * DDIM;
    const float* bp = bp1 + l * DDIM;
    float w2 = g_w2cs[l*DDIM + tid];
    bool pos = w2 > 0.f;
    unsigned bal = __ballot_sync(0xffffffffu, pos);
    int wp = __popc(bal & ((1u << lane) - 1u));
    if (!lane) cntP[wid] = __popc(bal);
    __syncthreads();
    int offP = 0, npos = 0;
    #pragma unroll
    for (int w = 0; w < 4; w++) {
        if (w < wid) offP += cntP[w];
        npos += cntP[w];
    }
    int offN = wid * 32 - offP;
    int wn = lane - wp;
    int dest = pos ? (offP + wp) : (npos + offN + wn);
    g_pe4[l*DDIM + dest] = make_float4(W[tid]*w2, W[DDIM+tid]*w2, W[2*DDIM+tid]*w2, bp[tid]*w2);
    if (tid == 0) g_npos[l] = npos;
}

// ================= GEMM: f32x2 packed, transposed W, BM=16 =================
// MODE: 0 = +bias fp32 out; 1 = +bias+Add; 2 = Res+gamma*(acc+bias); 3 = +bias bf16 out + fused qs/ks
// LNA: LayerNorm+ReLU on A rows (K=128); CAT: A assembled from [x_t | fused | temb]
template<int MODE, bool LNA, bool CAT>
__global__ void __launch_bounds__(128) gemm_v3(
    const float* __restrict__ A, int K, int KPp,
    const float* __restrict__ W,
    const float* __restrict__ bias,
    void* __restrict__ Cv,
    const float* __restrict__ Add,
    const float* __restrict__ Res,
    const float* __restrict__ gammaPtr,
    const float* __restrict__ lng, const float* __restrict__ lnb,
    const float* __restrict__ wq, const float* __restrict__ wk,
    const float* __restrict__ scal2,
    float* __restrict__ qs, float* __restrict__ ks,
    const float* __restrict__ xt, const float* __restrict__ te)
{
    extern __shared__ float sm[];
    float* As = sm;                 // 16 * KPp
    float* Wt = sm + 16 * KPp;      // 64 * KPp

    int tid = threadIdx.x, tx = tid & 31, wrp = tid >> 5;
    int row0 = blockIdx.x * 16, ny = blockIdx.y;

    // ---- A tile
    if (CAT) {
        for (int i = tid; i < 16*KPp; i += 128) {
            int rr = i / KPp, c = i - rr*KPp;
            int row = row0 + rr;
            float v = 0.f;
            if (c < 3)        v = xt[row*3 + c];
            else if (c < 131) v = A[(size_t)row*DDIM + (c-3)];
            else if (c < 259) v = te[(row >> 11)*DDIM + (c-131)];
            As[i] = v;
        }
    } else {
        int K4 = K >> 2, KP4 = KPp >> 2;
        const float4* A4 = (const float4*)A;
        float4* As4 = (float4*)As;
        for (int i = tid; i < 16*KP4; i += 128) {
            int rr = i / KP4, c = i - rr*KP4;
            As4[i] = (c < K4) ? A4[(size_t)(row0+rr)*K4 + c] : make_float4(0.f,0.f,0.f,0.f);
        }
    }

    // ---- W half, transposed into Wt[c][k]
    {
        int nblk = 16 * KPp;
        for (int i = tid; i < nblk; i += 128) {
            int c = i & 63, kb4 = i >> 6;
            int k0 = kb4 << 2;
            float w0 = (k0+0 < K) ? W[(size_t)(k0+0)*128 + ny*64 + c] : 0.f;
            float w1 = (k0+1 < K) ? W[(size_t)(k0+1)*128 + ny*64 + c] : 0.f;
            float w2 = (k0+2 < K) ? W[(size_t)(k0+2)*128 + ny*64 + c] : 0.f;
            float w3 = (k0+3 < K) ? W[(size_t)(k0+3)*128 + ny*64 + c] : 0.f;
            *(float4*)&Wt[c*KPp + k0] = make_float4(w0, w1, w2, w3);
        }
    }
    __syncthreads();

    // ---- optional LN+ReLU on A rows (K==128)
    if (LNA) {
        int rrow = tid >> 3, seg = tid & 7;
        float* rowp = As + rrow*KPp + seg*16;
        float s = 0.f;
        #pragma unroll
        for (int j = 0; j < 16; j++) s += rowp[j];
        s += __shfl_xor_sync(0xffffffffu, s, 1);
        s += __shfl_xor_sync(0xffffffffu, s, 2);
        s += __shfl_xor_sync(0xffffffffu, s, 4);
        float mean = s * 0.0078125f;
        float q = 0.f;
        #pragma unroll
        for (int j = 0; j < 16; j++) { float d = rowp[j] - mean; q = fmaf(d, d, q); }
        q += __shfl_xor_sync(0xffffffffu, q, 1);
        q += __shfl_xor_sync(0xffffffffu, q, 2);
        q += __shfl_xor_sync(0xffffffffu, q, 4);
        float rstd = rsqrtf(q * 0.0078125f + 1e-5f);
        #pragma unroll
        for (int j = 0; j < 16; j++) {
            int c = seg*16 + j;
            rowp[j] = fmaxf(fmaf((rowp[j]-mean)*rstd, __ldg(&lng[c]), __ldg(&lnb[c])), 0.f);
        }
        __syncthreads();
    }

    // ---- fused qs/ks (v-gemm, half 0)
    if (MODE == 3 && ny == 0) {
        int rrow = tid >> 3, seg = tid & 7;
        const float* rowp = As + rrow*KPp + seg*16;
        float dq = 0.f, dk = 0.f;
        #pragma unroll
        for (int j = 0; j < 16; j++) {
            float a = rowp[j];
            dq = fmaf(a, __ldg(&wq[seg*16+j]), dq);
            dk = fmaf(a, __ldg(&wk[seg*16+j]), dk);
        }
        dq += __shfl_xor_sync(0xffffffffu, dq, 1);
        dq += __shfl_xor_sync(0xffffffffu, dq, 2);
        dq += __shfl_xor_sync(0xffffffffu, dq, 4);
        dk += __shfl_xor_sync(0xffffffffu, dk, 1);
        dk += __shfl_xor_sync(0xffffffffu, dk, 2);
        dk += __shfl_xor_sync(0xffffffffu, dk, 4);
        if (seg == 0) {
            qs[row0 + rrow] = dq + __ldg(&scal2[0]);
            ks[row0 + rrow] = dk + __ldg(&scal2[1]);
        }
    }

    // ---- main loop
    ull acc[4][2];
    #pragma unroll
    for (int rr = 0; rr < 4; rr++) { acc[rr][0] = pk2(0.f, 0.f); acc[rr][1] = pk2(0.f, 0.f); }

    const float* a0 = As + (wrp*4+0)*KPp;
    const float* a1 = As + (wrp*4+1)*KPp;
    const float* a2 = As + (wrp*4+2)*KPp;
    const float* a3 = As + (wrp*4+3)*KPp;
    const float* w0p = Wt + tx*KPp;
    const float* w1p = Wt + (tx+32)*KPp;

    #pragma unroll 4
    for (int kb = 0; kb < KPp; kb += 4) {
        float4 wa = *(const float4*)&w0p[kb];
        float4 wb = *(const float4*)&w1p[kb];
        ull waL = pk2(wa.x, wa.y), waH = pk2(wa.z, wa.w);
        ull wbL = pk2(wb.x, wb.y), wbH = pk2(wb.z, wb.w);
        float4 v0 = *(const float4*)&a0[kb];
        float4 v1 = *(const float4*)&a1[kb];
        float4 v2 = *(const float4*)&a2[kb];
        float4 v3 = *(const float4*)&a3[kb];
        ull p0L = pk2(v0.x, v0.y), p0H = pk2(v0.z, v0.w);
        ull p1L = pk2(v1.x, v1.y), p1H = pk2(v1.z, v1.w);
        ull p2L = pk2(v2.x, v2.y), p2H = pk2(v2.z, v2.w);
        ull p3L = pk2(v3.x, v3.y), p3H = pk2(v3.z, v3.w);
        ffma2(acc[0][0], p0L, waL); ffma2(acc[0][0], p0H, waH);
        ffma2(acc[1][0], p1L, waL); ffma2(acc[1][0], p1H, waH);
        ffma2(acc[2][0], p2L, waL); ffma2(acc[2][0], p2H, waH);
        ffma2(acc[3][0], p3L, waL); ffma2(acc[3][0], p3H, waH);
        ffma2(acc[0][1], p0L, wbL); ffma2(acc[0][1], p0H, wbH);
        ffma2(acc[1][1], p1L, wbL); ffma2(acc[1][1], p1H, wbH);
        ffma2(acc[2][1], p2L, wbL); ffma2(acc[2][1], p2H, wbH);
        ffma2(acc[3][1], p3L, wbL); ffma2(acc[3][1], p3H, wbH);
    }

    // ---- epilogue
    int c0 = ny*64 + tx, c1 = c0 + 32;
    float b0 = __ldg(&bias[c0]), b1 = __ldg(&bias[c1]);
    float gmv = (MODE == 2) ? __ldg(gammaPtr) : 0.f;

    #pragma unroll
    for (int rr = 0; rr < 4; rr++) {
        int row = row0 + wrp*4 + rr;
        float2 s0 = upk2(acc[rr][0]);
        float2 s1 = upk2(acc[rr][1]);
        float v0 = s0.x + s0.y + b0;
        float v1 = s1.x + s1.y + b1;
        if (MODE == 1) {
            v0 += Add[(size_t)row*128 + c0];
            v1 += Add[(size_t)row*128 + c1];
        }
        if (MODE == 2) {
            v0 = fmaf(gmv, v0, Res[(size_t)row*128 + c0]);
            v1 = fmaf(gmv, v1, Res[(size_t)row*128 + c1]);
        }
        if (MODE == 3) {
            __nv_bfloat16* C = (__nv_bfloat16*)Cv;
            C[(size_t)row*128 + c0] = __float2bfloat16(v0);
            C[(size_t)row*128 + c1] = __float2bfloat16(v1);
        } else {
            float* C = (float*)Cv;
            C[(size_t)row*128 + c0] = v0;
            C[(size_t)row*128 + c1] = v1;
        }
    }
}

// ================= attention v4: scaled-sorted pe weights + bf16 v-gather =================
__global__ void __launch_bounds__(128) attn4(
    const float4* __restrict__ pe4, const int* __restrict__ nposPtr,
    const float* __restrict__ Wp1, const float* __restrict__ bp1,
    const float* __restrict__ scal)
{
    __shared__ float4 sp4[DDIM];
    __shared__ float4 relq[KNBR];
    __shared__ int    ids[KNBR];
    __shared__ float  red[8];
    __shared__ float  rv[4*DDIM];
    __shared__ float  rh[4*DDIM];

    int p = blockIdx.x, tid = threadIdx.x, lane = tid & 31, wrp = tid >> 5;

    sp4[tid] = __ldg(&pe4[tid]);

    size_t base = (size_t)p * KNBR + tid;
    float4 rq = g_rel4[base];
    int gm = g_idx[base];
    ids[tid] = gm;
    int npos = __ldg(nposPtr);
    __syncthreads();

    // ---- phase 1
    float dot = 0.f;
    int d = 0;
    #pragma unroll 4
    for (; d < npos; d++) {
        float4 w = sp4[d];
        float h = fmaf(rq.x, w.x, fmaf(rq.y, w.y, fmaf(rq.z, w.z, w.w)));
        dot += fmaxf(h, 0.f);
    }
    #pragma unroll 4
    for (; d < DDIM; d++) {
        float4 w = sp4[d];
        float h = fmaf(rq.x, w.x, fmaf(rq.y, w.y, fmaf(rq.z, w.z, w.w)));
        dot += fminf(h, 0.f);
    }
    float logit = g_qs[p] - g_ks[gm] + dot + __ldg(&scal[2]);

    // ---- phase 2: softmax over 128
    float mx = logit;
    #pragma unroll
    for (int o = 16; o; o >>= 1) mx = fmaxf(mx, __shfl_xor_sync(0xffffffffu, mx, o));
    if (!lane) red[wrp] = mx;
    __syncthreads();
    mx = fmaxf(fmaxf(red[0], red[1]), fmaxf(red[2], red[3]));
    float e = expf(logit - mx);
    float ss = e;
    #pragma unroll
    for (int o = 16; o; o >>= 1) ss += __shfl_xor_sync(0xffffffffu, ss, o);
    if (!lane) red[4 + wrp] = ss;
    __syncthreads();
    ss = red[4] + red[5] + red[6] + red[7];
    rq.w = e / ss;
    relq[tid] = rq;
    __syncthreads();

    // ---- phase 3: warp wrp -> k in [wrp*32, +32); lane -> 4 cols
    float4 WX = __ldg((const float4*)&Wp1[lane*4]);
    float4 WY = __ldg((const float4*)&Wp1[DDIM + lane*4]);
    float4 WZ = __ldg((const float4*)&Wp1[2*DDIM + lane*4]);
    float4 BV = __ldg((const float4*)&bp1[lane*4]);

    float av0=0.f, av1=0.f, av2=0.f, av3=0.f;
    float ah0=0.f, ah1=0.f, ah2=0.f, ah3=0.f;
    int kbase = wrp * 32;
    const __nv_bfloat16* vbase = g_vh + lane*4;
    #pragma unroll 4
    for (int j = 0; j < 32; j++) {
        float4 rk = relq[kbase + j];
        int id = ids[kbase + j];
        uint2 raw = __ldg((const uint2*)(vbase + (size_t)id * DDIM));
        float2 f01 = __bfloat1622float2(*(__nv_bfloat162*)&raw.x);
        float2 f23 = __bfloat1622float2(*(__nv_bfloat162*)&raw.y);
        float a = rk.w;
        float h0 = fmaxf(fmaf(rk.x,WX.x,fmaf(rk.y,WY.x,fmaf(rk.z,WZ.x,BV.x))), 0.f);
        float h1 = fmaxf(fmaf(rk.x,WX.y,fmaf(rk.y,WY.y,fmaf(rk.z,WZ.y,BV.y))), 0.f);
        float h2 = fmaxf(fmaf(rk.x,WX.z,fmaf(rk.y,WY.z,fmaf(rk.z,WZ.z,BV.z))), 0.f);
        float h3 = fmaxf(fmaf(rk.x,WX.w,fmaf(rk.y,WY.w,fmaf(rk.z,WZ.w,BV.w))), 0.f);
        ah0 = fmaf(a, h0, ah0); ah1 = fmaf(a, h1, ah1);
        ah2 = fmaf(a, h2, ah2); ah3 = fmaf(a, h3, ah3);
        av0 = fmaf(a, f01.x, av0); av1 = fmaf(a, f01.y, av1);
        av2 = fmaf(a, f23.x, av2); av3 = fmaf(a, f23.y, av3);
    }
    *(float4*)&rv[wrp*DDIM + lane*4] = make_float4(av0, av1, av2, av3);
    *(float4*)&rh[wrp*DDIM + lane*4] = make_float4(ah0, ah1, ah2, ah3);
    __syncthreads();

    float sv = rv[tid] + rv[DDIM+tid] + rv[2*DDIM+tid] + rv[3*DDIM+tid];
    float sh = rh[tid] + rh[DDIM+tid] + rh[2*DDIM+tid] + rh[3*DDIM+tid];
    g_aggv[(size_t)p*DDIM + tid] = sv;
    g_aggh[(size_t)p*DDIM + tid] = sh;
}

// ================= timestep embedding MLP =================
__global__ void temb_kernel(const int* __restrict__ t,
                            const float* __restrict__ tW1, const float* __restrict__ tb1,
                            const float* __restrict__ tW2, const float* __restrict__ tb2) {
    __shared__ float emb[128], h1[128];
    int b = blockIdx.x, d = threadIdx.x;
    float tv = (float)t[b];
    if (d < 64) {
        float f = expf(-logf(10000.f) * (float)d / 63.f);
        float arg = tv * f;
        emb[d] = sinf(arg);
        emb[d + 64] = cosf(arg);
    }
    __syncthreads();
    float a = tb1[d];
    for (int i = 0; i < 128; i++) a = fmaf(emb[i], tW1[i*128 + d], a);
    h1[d] = fmaxf(a, 0.f);
    __syncthreads();
    float c = tb2[d];
    for (int i = 0; i < 128; i++) c = fmaf(h1[i], tW2[i*128 + d], c);
    g_temb[b*128 + d] = c;
}

// ================= final LN+ReLU+proj =================
__global__ void out_kernel(const float* __restrict__ g2, const float* __restrict__ be2,
                           const float* __restrict__ W3, const float* __restrict__ b3,
                           float* __restrict__ out) {
    int p = blockIdx.x * 8 + (threadIdx.x >> 5);
    int lane = threadIdx.x & 31;
    float4 f = ((const float4*)(g_h2 + (size_t)p * DDIM))[lane];
    float s = f.x + f.y + f.z + f.w;
    #pragma unroll
    for (int o = 16; o; o >>= 1) s += __shfl_xor_sync(0xffffffffu, s, o);
    float mean = s * 0.0078125f;
    float d0 = f.x-mean, d1 = f.y-mean, d2 = f.z-mean, d3 = f.w-mean;
    float q = d0*d0 + d1*d1 + d2*d2 + d3*d3;
    #pragma unroll
    for (int o = 16; o; o >>= 1) q += __shfl_xor_sync(0xffffffffu, q, o);
    float rstd = rsqrtf(q * 0.0078125f + 1e-5f);
    int i0 = lane * 4;
    float4 gg = *(const float4*)&g2[i0];
    float4 bb = *(const float4*)&be2[i0];
    float v0 = fmaxf(fmaf(d0*rstd, gg.x, bb.x), 0.f);
    float v1 = fmaxf(fmaf(d1*rstd, gg.y, bb.y), 0.f);
    float v2 = fmaxf(fmaf(d2*rstd, gg.z, bb.z), 0.f);
    float v3 = fmaxf(fmaf(d3*rstd, gg.w, bb.w), 0.f);
    float a0 = v0*W3[i0*3+0] + v1*W3[(i0+1)*3+0] + v2*W3[(i0+2)*3+0] + v3*W3[(i0+3)*3+0];
    float a1 = v0*W3[i0*3+1] + v1*W3[(i0+1)*3+1] + v2*W3[(i0+2)*3+1] + v3*W3[(i0+3)*3+1];
    float a2 = v0*W3[i0*3+2] + v1*W3[(i0+1)*3+2] + v2*W3[(i0+2)*3+2] + v3*W3[(i0+3)*3+2];
    #pragma unroll
    for (int o = 16; o; o >>= 1) {
        a0 += __shfl_xor_sync(0xffffffffu, a0, o);
        a1 += __shfl_xor_sync(0xffffffffu, a1, o);
        a2 += __shfl_xor_sync(0xffffffffu, a2, o);
    }
    if (!lane) {
        out[p*3+0] = a0 + b3[0];
        out[p*3+1] = a1 + b3[1];
        out[p*3+2] = a2 + b3[2];
    }
}

#define KPP128 132
#define KPP259 260
#define GS(KPp) (80 * (KPp) * 4)

extern "C" void kernel_launch(void* const* d_in, const int* in_sizes, int n_in,
                              void* d_out, int out_size) {
    const float* xyz   = (const float*)d_in[0];
    const float* feat  = (const float*)d_in[1];
    const float* x_t   = (const float*)d_in[2];
    const int*   t     = (const int*)  d_in[3];
    const float* Wq    = (const float*)d_in[4];
    const float* bq    = (const float*)d_in[5];
    const float* Wk    = (const float*)d_in[6];
    const float* bk    = (const float*)d_in[7];
    const float* Wv    = (const float*)d_in[8];
    const float* bv    = (const float*)d_in[9];
    const float* Wp1   = (const float*)d_in[10];
    const float* bp1   = (const float*)d_in[11];
    const float* Wp2   = (const float*)d_in[12];
    const float* bp2   = (const float*)d_in[13];
    const float* gamma = (const float*)d_in[14];
    const float* Wproj = (const float*)d_in[15];
    const float* bproj = (const float*)d_in[16];
    const float* tW1   = (const float*)d_in[17];
    const float* tb1   = (const float*)d_in[18];
    const float* tW2   = (const float*)d_in[19];
    const float* tb2   = (const float*)d_in[20];
    const float* nW1   = (const float*)d_in[21];
    const float* nb1   = (const float*)d_in[22];
    const float* ng1   = (const float*)d_in[23];
    const float* nbe1  = (const float*)d_in[24];
    const float* nW2   = (const float*)d_in[25];
    const float* nb2   = (const float*)d_in[26];
    const float* ng2   = (const float*)d_in[27];
    const float* nbe2  = (const float*)d_in[28];
    const float* nW3   = (const float*)d_in[29];
    const float* nb3   = (const float*)d_in[30];

    cudaFuncSetAttribute(gemm_v3<3,false,false>, cudaFuncAttributeMaxDynamicSharedMemorySize, GS(KPP128));
    cudaFuncSetAttribute(gemm_v3<1,false,false>, cudaFuncAttributeMaxDynamicSharedMemorySize, GS(KPP128));
    cudaFuncSetAttribute(gemm_v3<2,false,false>, cudaFuncAttributeMaxDynamicSharedMemorySize, GS(KPP128));
    cudaFuncSetAttribute(gemm_v3<0,false,true>,  cudaFuncAttributeMaxDynamicSharedMemorySize, GS(KPP259));
    cudaFuncSetAttribute(gemm_v3<0,true,false>,  cudaFuncAttributeMaxDynamicSharedMemorySize, GS(KPP128));

    float *paggv, *paggh, *pt1, *pfA, *pfB, *ph1, *ph2, *pqs, *pks;
    float *pwq, *pwk, *psc, *ptemb;
    float4 *ppe4; int *pnpos;
    __nv_bfloat16 *pvh;
    cudaGetSymbolAddress((void**)&pvh,   g_vh);
    cudaGetSymbolAddress((void**)&paggv, g_aggv);
    cudaGetSymbolAddress((void**)&paggh, g_aggh);
    cudaGetSymbolAddress((void**)&pt1,   g_t1);
    cudaGetSymbolAddress((void**)&pfA,   g_fA);
    cudaGetSymbolAddress((void**)&pfB,   g_fB);
    cudaGetSymbolAddress((void**)&ph1,   g_h1);
    cudaGetSymbolAddress((void**)&ph2,   g_h2);
    cudaGetSymbolAddress((void**)&pqs,   g_qs);
    cudaGetSymbolAddress((void**)&pks,   g_ks);
    cudaGetSymbolAddress((void**)&pwq,   g_wqcs);
    cudaGetSymbolAddress((void**)&pwk,   g_wkcs);
    cudaGetSymbolAddress((void**)&psc,   g_scal);
    cudaGetSymbolAddress((void**)&ppe4,  g_pe4);
    cudaGetSymbolAddress((void**)&pnpos, g_npos);
    cudaGetSymbolAddress((void**)&ptemb, g_temb);

    knn_kernel<<<PP, 256>>>(xyz);
    prep_all<<<dim3(NLAYER,4), 128>>>(Wq, bq, Wk, bk, Wp2, bp2);
    prep2<<<NLAYER, 128>>>(Wp1, bp1);
    temb_kernel<<<BB, 128>>>(t, tW1, tb1, tW2, tb2);

    dim3 ggrid(PP/16, 2);
    const float* cur = feat;
    float* bufs[2] = { pfA, pfB };
    for (int l = 0; l < NLAYER; l++) {
        gemm_v3<3,false,false><<<ggrid, 128, GS(KPP128)>>>(cur, 128, KPP128,
            Wv + (size_t)l*DDIM*DDIM, bv + l*DDIM, pvh,
            nullptr, nullptr, nullptr, nullptr, nullptr,
            pwq + l*DDIM, pwk + l*DDIM, psc + l*4, pqs, pks,
            nullptr, nullptr);
        attn4<<<PP, 128>>>(ppe4 + l*DDIM, pnpos + l,
                           Wp1 + (size_t)l*3*DDIM, bp1 + l*DDIM, psc + l*4);
        gemm_v3<1,false,false><<<ggrid, 128, GS(KPP128)>>>(paggh, 128, KPP128,
            Wp2 + (size_t)l*DDIM*DDIM, bp2 + l*DDIM, pt1,
            paggv, nullptr, nullptr, nullptr, nullptr,
            nullptr, nullptr, nullptr, nullptr, nullptr,
            nullptr, nullptr);
        float* nxt = bufs[l & 1];
        gemm_v3<2,false,false><<<ggrid, 128, GS(KPP128)>>>(pt1, 128, KPP128,
            Wproj + (size_t)l*DDIM*DDIM, bproj + l*DDIM, nxt,
            nullptr, cur, gamma + l, nullptr, nullptr,
            nullptr, nullptr, nullptr, nullptr, nullptr,
            nullptr, nullptr);
        cur = nxt;
    }

    gemm_v3<0,false,true><<<ggrid, 128, GS(KPP259)>>>(cur, HCAT, KPP259,
        nW1, nb1, ph1,
        nullptr, nullptr, nullptr, nullptr, nullptr,
        nullptr, nullptr, nullptr, nullptr, nullptr,
        x_t, ptemb);
    gemm_v3<0,true,false><<<ggrid, 128, GS(KPP128)>>>(ph1, 128, KPP128,
        nW2, nb2, ph2,
        nullptr, nullptr, nullptr, ng1, nbe1,
        nullptr, nullptr, nullptr, nullptr, nullptr,
        nullptr, nullptr);
    out_kernel<<<PP/8, 256>>>(ng2, nbe2, nW3, nb3, (float*)d_out);
}